// round 7
// baseline (speedup 1.0000x reference)
#include <cuda_runtime.h>
#include <cstdint>
#include <math.h>

// Problem constants
#define BB 4
#define SS 2048
#define DD 512
#define HH 8
#define DKK 64
#define FFF 2048
#define MM (BB * SS)   // 8192 rows

// ---------------------------------------------------------------------------
// Scratch (device globals — no allocation allowed)
// ---------------------------------------------------------------------------
__device__ float g_q  [MM * DD];
__device__ float g_k  [MM * DD];
__device__ float g_v  [MM * DD];
__device__ float g_ctx[MM * DD];
__device__ float g_h  [MM * DD];
__device__ float g_ffn[MM * FFF];

// ---------------------------------------------------------------------------
// Helpers
// ---------------------------------------------------------------------------
__device__ __forceinline__ float to_tf32(float x) {
    float r; asm("cvt.rna.tf32.f32 %0, %1;" : "=f"(r) : "f"(x)); return r;
}

__device__ __forceinline__ void mma_tf32(float c[4], const uint32_t a[4], const uint32_t b[2]) {
    asm volatile(
        "mma.sync.aligned.m16n8k8.row.col.f32.tf32.tf32.f32 "
        "{%0,%1,%2,%3}, {%4,%5,%6,%7}, {%8,%9}, {%0,%1,%2,%3};"
        : "+f"(c[0]), "+f"(c[1]), "+f"(c[2]), "+f"(c[3])
        : "r"(a[0]), "r"(a[1]), "r"(a[2]), "r"(a[3]), "r"(b[0]), "r"(b[1]));
}

#define SK 136   // smem row stride in floats (conflict-free for frag LDS + STS)

// A fragment (m16k8): a0 row=lane>>2 col=lane&3; a1 row+8; a2 col+4; a3 row+8,col+4
__device__ __forceinline__ void load_afrag(uint32_t a[4], const float* base,
                                           int krow, int mrow, int lane) {
    const float* p = base + (krow + (lane & 3)) * SK + mrow + (lane >> 2);
    a[0] = __float_as_uint(p[0]);
    a[1] = __float_as_uint(p[8]);
    a[2] = __float_as_uint(p[4 * SK]);
    a[3] = __float_as_uint(p[4 * SK + 8]);
}
// B fragment (k8n8): b0 row(k)=lane&3 col(n)=lane>>2; b1 k+4
__device__ __forceinline__ void load_bfrag(uint32_t b[2], const float* base,
                                           int krow, int ncol, int lane) {
    const float* p = base + (krow + (lane & 3)) * SK + ncol + (lane >> 2);
    b[0] = __float_as_uint(p[0]);
    b[1] = __float_as_uint(p[4 * SK]);
}

// ---------------------------------------------------------------------------
// tf32x3 HMMA GEMM: C[M,N] = A[M,K] @ B[K,N] + bias (+resid) (opt relu)
// CTA tile 128x128, BK=16, 256 threads (8 warps as 2m x 4n of 64x32 tiles).
// Double-buffered smem; hi/lo tf32 split stored as fp32.
// ---------------------------------------------------------------------------
#define TILE_F (16 * SK)                 // floats per array per stage (2176)
#define SMEM_BYTES (8 * TILE_F * 4)      // 4 arrays x 2 stages = 69632 B

__global__ __launch_bounds__(256, 2) void tc_gemm(
    const float* __restrict__ A, const float* __restrict__ Bw,
    const float* __restrict__ bias, const float* __restrict__ resid,
    float* __restrict__ C, int N, int K, int relu)
{
    extern __shared__ float sm[];
    const int tid  = threadIdx.x;
    const int lane = tid & 31;
    const int wid  = tid >> 5;
    const int m0 = blockIdx.y * 128, n0 = blockIdx.x * 128;
    const int wm = (wid & 1) * 64;       // warp m offset
    const int wn = (wid >> 1) * 32;      // warp n offset

    // gmem staging pattern
    const int am  = tid & 127;           // A row within tile
    const int akq = tid >> 7;            // A k-quad base (0/1)
    const int bn4 = (tid & 31) * 4;      // B col (float4)
    const int bk  = tid >> 5;            // B k row (0..7), +8 for it=1

    float cfr[4][4][4];
#pragma unroll
    for (int t = 0; t < 4; t++)
#pragma unroll
        for (int u = 0; u < 4; u++)
#pragma unroll
            for (int e = 0; e < 4; e++) cfr[t][u][e] = 0.f;

    float4 aR[2], bR[2];

    const int nst = K >> 4;              // BK = 16

    // ---- stage 0 load + store ----
#pragma unroll
    for (int it = 0; it < 2; it++) {
        aR[it] = *(const float4*)(A + (size_t)(m0 + am) * K + (akq + 2 * it) * 4);
        bR[it] = *(const float4*)(Bw + (size_t)(bk + it * 8) * N + n0 + bn4);
    }
    {
        float* AH = sm;            float* AL = sm + TILE_F;
        float* BH = sm + 2*TILE_F; float* BL = sm + 3*TILE_F;
#pragma unroll
        for (int it = 0; it < 2; it++) {
            const int k4 = (akq + 2 * it) * 4;
            const float av[4] = { aR[it].x, aR[it].y, aR[it].z, aR[it].w };
#pragma unroll
            for (int j = 0; j < 4; j++) {
                const float h = to_tf32(av[j]);
                AH[(k4 + j) * SK + am] = h;
                AL[(k4 + j) * SK + am] = to_tf32(av[j] - h);
            }
            const int kb = bk + it * 8;
            float4 h4, l4;
            h4.x = to_tf32(bR[it].x); l4.x = to_tf32(bR[it].x - h4.x);
            h4.y = to_tf32(bR[it].y); l4.y = to_tf32(bR[it].y - h4.y);
            h4.z = to_tf32(bR[it].z); l4.z = to_tf32(bR[it].z - h4.z);
            h4.w = to_tf32(bR[it].w); l4.w = to_tf32(bR[it].w - h4.w);
            *(float4*)(BH + kb * SK + bn4) = h4;
            *(float4*)(BL + kb * SK + bn4) = l4;
        }
    }
    __syncthreads();

    for (int i = 0; i < nst; i++) {
        // prefetch next stage into regs
        if (i + 1 < nst) {
            const int k0 = (i + 1) << 4;
#pragma unroll
            for (int it = 0; it < 2; it++) {
                aR[it] = *(const float4*)(A + (size_t)(m0 + am) * K + k0 + (akq + 2 * it) * 4);
                bR[it] = *(const float4*)(Bw + (size_t)(k0 + bk + it * 8) * N + n0 + bn4);
            }
        }

        // compute current stage (2 k-steps of 8)
        {
            const float* AH = sm + (size_t)(i & 1) * 4 * TILE_F;
            const float* AL = AH + TILE_F;
            const float* BH = AH + 2 * TILE_F;
            const float* BL = AH + 3 * TILE_F;
#pragma unroll
            for (int ks = 0; ks < 2; ks++) {
                const int krow = ks * 8;
                uint32_t af[4][4], bf[4][2];
                // hi x hi
#pragma unroll
                for (int t = 0; t < 4; t++) load_afrag(af[t], AH, krow, wm + t * 16, lane);
#pragma unroll
                for (int u = 0; u < 4; u++) load_bfrag(bf[u], BH, krow, wn + u * 8, lane);
#pragma unroll
                for (int t = 0; t < 4; t++)
#pragma unroll
                    for (int u = 0; u < 4; u++) mma_tf32(cfr[t][u], af[t], bf[u]);
                // hi x lo (reuse A hi)
#pragma unroll
                for (int u = 0; u < 4; u++) load_bfrag(bf[u], BL, krow, wn + u * 8, lane);
#pragma unroll
                for (int t = 0; t < 4; t++)
#pragma unroll
                    for (int u = 0; u < 4; u++) mma_tf32(cfr[t][u], af[t], bf[u]);
                // lo x hi
#pragma unroll
                for (int t = 0; t < 4; t++) load_afrag(af[t], AL, krow, wm + t * 16, lane);
#pragma unroll
                for (int u = 0; u < 4; u++) load_bfrag(bf[u], BH, krow, wn + u * 8, lane);
#pragma unroll
                for (int t = 0; t < 4; t++)
#pragma unroll
                    for (int u = 0; u < 4; u++) mma_tf32(cfr[t][u], af[t], bf[u]);
            }
        }

        // store next stage to the other buffer
        if (i + 1 < nst) {
            float* AH = sm + (size_t)((i + 1) & 1) * 4 * TILE_F;
            float* AL = AH + TILE_F;
            float* BH = AH + 2 * TILE_F;
            float* BL = AH + 3 * TILE_F;
#pragma unroll
            for (int it = 0; it < 2; it++) {
                const int k4 = (akq + 2 * it) * 4;
                const float av[4] = { aR[it].x, aR[it].y, aR[it].z, aR[it].w };
#pragma unroll
                for (int j = 0; j < 4; j++) {
                    const float h = to_tf32(av[j]);
                    AH[(k4 + j) * SK + am] = h;
                    AL[(k4 + j) * SK + am] = to_tf32(av[j] - h);
                }
                const int kb = bk + it * 8;
                float4 h4, l4;
                h4.x = to_tf32(bR[it].x); l4.x = to_tf32(bR[it].x - h4.x);
                h4.y = to_tf32(bR[it].y); l4.y = to_tf32(bR[it].y - h4.y);
                h4.z = to_tf32(bR[it].z); l4.z = to_tf32(bR[it].z - h4.z);
                h4.w = to_tf32(bR[it].w); l4.w = to_tf32(bR[it].w - h4.w);
                *(float4*)(BH + kb * SK + bn4) = h4;
                *(float4*)(BL + kb * SK + bn4) = l4;
            }
        }
        __syncthreads();
    }

    // ---- epilogue: bias (+relu) (+resid), write C ----
#pragma unroll
    for (int t = 0; t < 4; t++) {
        const int r0 = m0 + wm + t * 16 + (lane >> 2);
        const int r1 = r0 + 8;
#pragma unroll
        for (int u = 0; u < 4; u++) {
            const int c = n0 + wn + u * 8 + 2 * (lane & 3);
            const float2 b2 = *(const float2*)(bias + c);
            float o0 = cfr[t][u][0] + b2.x, o1 = cfr[t][u][1] + b2.y;
            float o2 = cfr[t][u][2] + b2.x, o3 = cfr[t][u][3] + b2.y;
            if (relu) {
                o0 = fmaxf(o0, 0.f); o1 = fmaxf(o1, 0.f);
                o2 = fmaxf(o2, 0.f); o3 = fmaxf(o3, 0.f);
            }
            if (resid) {
                const float2 ra = *(const float2*)(resid + (size_t)r0 * N + c);
                const float2 rb = *(const float2*)(resid + (size_t)r1 * N + c);
                o0 += ra.x; o1 += ra.y; o2 += rb.x; o3 += rb.y;
            }
            *(float2*)(C + (size_t)r0 * N + c) = make_float2(o0, o1);
            *(float2*)(C + (size_t)r1 * N + c) = make_float2(o2, o3);
        }
    }
}

// ---------------------------------------------------------------------------
// Causal flash attention (unchanged).
// ---------------------------------------------------------------------------
__global__ __launch_bounds__(128) void attn_kernel(
    const float* __restrict__ Q, const float* __restrict__ K,
    const float* __restrict__ V, float* __restrict__ O)
{
    const int qb = blockIdx.x;
    const int h  = blockIdx.y;
    const int b  = blockIdx.z;
    const int tid  = threadIdx.x;
    const int qi   = tid >> 1;
    const int half = tid & 1;
    const int d0   = half * 32;
    const int qrow = qb * 64 + qi;

    __shared__ float Ks[64][64];
    __shared__ float Vs[64][64];

    float qreg[32];
    {
        const float sc = 0.125f;
        const float* qp = Q + ((size_t)b * SS + qrow) * DD + h * DKK + d0;
#pragma unroll
        for (int i = 0; i < 8; i++) {
            float4 t = *(const float4*)(qp + 4 * i);
            qreg[4*i+0] = t.x * sc; qreg[4*i+1] = t.y * sc;
            qreg[4*i+2] = t.z * sc; qreg[4*i+3] = t.w * sc;
        }
    }

    float acc[32];
#pragma unroll
    for (int d = 0; d < 32; d++) acc[d] = 0.f;
    float m = -1e30f, l = 0.f;

    const int ntiles = qb + 1;
    for (int kt = 0; kt < ntiles; kt++) {
        __syncthreads();
        const size_t base = ((size_t)b * SS + (size_t)kt * 64) * DD + h * DKK;
#pragma unroll
        for (int it = 0; it < 8; it++) {
            const int i = tid + it * 128;
            const int row = i >> 4;
            const int c4  = (i & 15) * 4;
            *(float4*)&Ks[row][c4] = *(const float4*)(K + base + (size_t)row * DD + c4);
            *(float4*)&Vs[row][c4] = *(const float4*)(V + base + (size_t)row * DD + c4);
        }
        __syncthreads();

        float s[64];
#pragma unroll
        for (int j = 0; j < 64; j++) {
            const float4* kr = (const float4*)&Ks[j][d0];
            float p = 0.f;
#pragma unroll
            for (int i = 0; i < 8; i++) {
                float4 t = kr[i];
                p += qreg[4*i+0]*t.x + qreg[4*i+1]*t.y
                   + qreg[4*i+2]*t.z + qreg[4*i+3]*t.w;
            }
            s[j] = p;
        }
#pragma unroll
        for (int j = 0; j < 64; j++)
            s[j] += __shfl_xor_sync(0xffffffffu, s[j], 1);

        if (kt == qb) {
#pragma unroll
            for (int j = 0; j < 64; j++)
                if (j > qi) s[j] = -1e30f;
        }

        float mt = m;
#pragma unroll
        for (int j = 0; j < 64; j++) mt = fmaxf(mt, s[j]);
        const float alpha = __expf(m - mt);
        m = mt;
        l *= alpha;
#pragma unroll
        for (int d = 0; d < 32; d++) acc[d] *= alpha;

#pragma unroll
        for (int j = 0; j < 64; j++) {
            const float p = __expf(s[j] - m);
            l += p;
            const float4* vr = (const float4*)&Vs[j][d0];
#pragma unroll
            for (int i = 0; i < 8; i++) {
                float4 t = vr[i];
                acc[4*i+0] += p * t.x; acc[4*i+1] += p * t.y;
                acc[4*i+2] += p * t.z; acc[4*i+3] += p * t.w;
            }
        }
    }

    const float inv = 1.f / l;
    float* op = O + ((size_t)b * SS + qrow) * DD + h * DKK + d0;
#pragma unroll
    for (int i = 0; i < 8; i++) {
        float4 t;
        t.x = acc[4*i+0] * inv; t.y = acc[4*i+1] * inv;
        t.z = acc[4*i+2] * inv; t.w = acc[4*i+3] * inv;
        *(float4*)(op + 4 * i) = t;
    }
}

// ---------------------------------------------------------------------------
// LayerNorm over last dim (512). One block (128 threads) per row.
// ---------------------------------------------------------------------------
__device__ __forceinline__ float block_sum(float v) {
    __shared__ float red[4];
#pragma unroll
    for (int o = 16; o; o >>= 1) v += __shfl_xor_sync(0xffffffffu, v, o);
    const int lane = threadIdx.x & 31, wid = threadIdx.x >> 5;
    if (lane == 0) red[wid] = v;
    __syncthreads();
    float r = (red[0] + red[1]) + (red[2] + red[3]);
    __syncthreads();
    return r;
}

__global__ __launch_bounds__(128) void ln_kernel(
    const float* __restrict__ X, const float* __restrict__ g,
    const float* __restrict__ be, float* __restrict__ out)
{
    const int row = blockIdx.x;
    const int tid = threadIdx.x;
    const float4 v = ((const float4*)(X + (size_t)row * DD))[tid];

    float s = block_sum(v.x + v.y + v.z + v.w);
    const float mu = s * (1.f / DD);
    const float dx = v.x - mu, dy = v.y - mu, dz = v.z - mu, dw = v.w - mu;
    float sq = block_sum(dx*dx + dy*dy + dz*dz + dw*dw);
    const float rstd = rsqrtf(sq * (1.f / DD) + 1e-5f);

    const float4 gv  = ((const float4*)g)[tid];
    const float4 bv  = ((const float4*)be)[tid];
    float4 o;
    o.x = dx * rstd * gv.x + bv.x;
    o.y = dy * rstd * gv.y + bv.y;
    o.z = dz * rstd * gv.z + bv.z;
    o.w = dw * rstd * gv.w + bv.w;
    ((float4*)(out + (size_t)row * DD))[tid] = o;
}

// ---------------------------------------------------------------------------
// Launch
// ---------------------------------------------------------------------------
static void run_tc_gemm(const float* A, const float* B, const float* bias,
                        const float* resid, float* C, int M, int N, int K, int relu)
{
    dim3 grid(N / 128, M / 128), block(256);
    tc_gemm<<<grid, block, SMEM_BYTES>>>(A, B, bias, resid, C, N, K, relu);
}

extern "C" void kernel_launch(void* const* d_in, const int* in_sizes, int n_in,
                              void* d_out, int out_size)
{
    (void)in_sizes; (void)n_in; (void)out_size;
    const float* x   = (const float*)d_in[0];
    // d_in[1] = mask (deterministic causal tril) — applied analytically
    const float* wq  = (const float*)d_in[2];
    const float* bq  = (const float*)d_in[3];
    const float* wk  = (const float*)d_in[4];
    const float* bk  = (const float*)d_in[5];
    const float* wv  = (const float*)d_in[6];
    const float* bv  = (const float*)d_in[7];
    const float* wo  = (const float*)d_in[8];
    const float* bo  = (const float*)d_in[9];
    const float* w1  = (const float*)d_in[10];
    const float* b1  = (const float*)d_in[11];
    const float* w2  = (const float*)d_in[12];
    const float* b2  = (const float*)d_in[13];
    const float* g1  = (const float*)d_in[14];
    const float* be1 = (const float*)d_in[15];
    const float* g2  = (const float*)d_in[16];
    const float* be2 = (const float*)d_in[17];
    float* out = (float*)d_out;

    float *q, *k, *v, *ctx, *h, *ffn;
    cudaGetSymbolAddress((void**)&q,   g_q);
    cudaGetSymbolAddress((void**)&k,   g_k);
    cudaGetSymbolAddress((void**)&v,   g_v);
    cudaGetSymbolAddress((void**)&ctx, g_ctx);
    cudaGetSymbolAddress((void**)&h,   g_h);
    cudaGetSymbolAddress((void**)&ffn, g_ffn);

    cudaFuncSetAttribute(tc_gemm, cudaFuncAttributeMaxDynamicSharedMemorySize, SMEM_BYTES);

    // QKV projections (HMMA tf32x3)
    run_tc_gemm(x, wq, bq, nullptr, q, MM, DD, DD, 0);
    run_tc_gemm(x, wk, bk, nullptr, k, MM, DD, DD, 0);
    run_tc_gemm(x, wv, bv, nullptr, v, MM, DD, DD, 0);

    // Causal attention -> ctx [B,S,D]
    attn_kernel<<<dim3(SS / 64, HH, BB), 128>>>(q, k, v, ctx);

    // Output projection + residual (x) -> reuse q as pre-LN buffer
    run_tc_gemm(ctx, wo, bo, x, q, MM, DD, DD, 0);
    ln_kernel<<<MM, 128>>>(q, g1, be1, h);

    // FFN
    run_tc_gemm(h,   w1, b1, nullptr, ffn, MM, FFF, DD, 1);
    run_tc_gemm(ffn, w2, b2, h,       q,   MM, DD, FFF, 0);
    ln_kernel<<<MM, 128>>>(q, g2, be2, out);
}

// round 8
// speedup vs baseline: 1.5704x; 1.5704x over previous
#include <cuda_runtime.h>
#include <cstdint>
#include <math.h>

// Problem constants
#define BB 4
#define SS 2048
#define DD 512
#define HH 8
#define DKK 64
#define FFF 2048
#define MM (BB * SS)   // 8192 rows

// ---------------------------------------------------------------------------
// Scratch (device globals — no allocation allowed)
// ---------------------------------------------------------------------------
__device__ float g_q  [MM * DD];
__device__ float g_k  [MM * DD];
__device__ float g_v  [MM * DD];
__device__ float g_ctx[MM * DD];
__device__ float g_h  [MM * DD];
__device__ float g_ffn[MM * FFF];

// ---------------------------------------------------------------------------
// Helpers
// ---------------------------------------------------------------------------
__device__ __forceinline__ float to_tf32(float x) {
    float r; asm("cvt.rna.tf32.f32 %0, %1;" : "=f"(r) : "f"(x)); return r;
}

__device__ __forceinline__ void mma_tf32(float c[4], const uint32_t a[4], const uint32_t b[2]) {
    asm volatile(
        "mma.sync.aligned.m16n8k8.row.col.f32.tf32.tf32.f32 "
        "{%0,%1,%2,%3}, {%4,%5,%6,%7}, {%8,%9}, {%0,%1,%2,%3};"
        : "+f"(c[0]), "+f"(c[1]), "+f"(c[2]), "+f"(c[3])
        : "r"(a[0]), "r"(a[1]), "r"(a[2]), "r"(a[3]), "r"(b[0]), "r"(b[1]));
}

// Generic fragment loaders (A stored k-major [k][m], B stored [k][n])
__device__ __forceinline__ void ldaf(uint32_t a[4], const float* base,
                                     int krow, int mrow, int lane, int st) {
    const float* p = base + (krow + (lane & 3)) * st + mrow + (lane >> 2);
    a[0] = __float_as_uint(p[0]);
    a[1] = __float_as_uint(p[8]);
    a[2] = __float_as_uint(p[4 * st]);
    a[3] = __float_as_uint(p[4 * st + 8]);
}
__device__ __forceinline__ void ldbf(uint32_t b[2], const float* base,
                                     int krow, int ncol, int lane, int st) {
    const float* p = base + (krow + (lane & 3)) * st + ncol + (lane >> 2);
    b[0] = __float_as_uint(p[0]);
    b[1] = __float_as_uint(p[4 * st]);
}

#define SK 136   // gemm smem row stride in floats

// ---------------------------------------------------------------------------
// tf32x3 HMMA GEMM (unchanged, validated): C = A@B + bias (+resid) (opt relu)
// ---------------------------------------------------------------------------
#define TILE_F (16 * SK)
#define SMEM_BYTES (8 * TILE_F * 4)

__global__ __launch_bounds__(256, 2) void tc_gemm(
    const float* __restrict__ A, const float* __restrict__ Bw,
    const float* __restrict__ bias, const float* __restrict__ resid,
    float* __restrict__ C, int N, int K, int relu)
{
    extern __shared__ float sm[];
    const int tid  = threadIdx.x;
    const int lane = tid & 31;
    const int wid  = tid >> 5;
    const int m0 = blockIdx.y * 128, n0 = blockIdx.x * 128;
    const int wm = (wid & 1) * 64;
    const int wn = (wid >> 1) * 32;

    const int am  = tid & 127;
    const int akq = tid >> 7;
    const int bn4 = (tid & 31) * 4;
    const int bk  = tid >> 5;

    float cfr[4][4][4];
#pragma unroll
    for (int t = 0; t < 4; t++)
#pragma unroll
        for (int u = 0; u < 4; u++)
#pragma unroll
            for (int e = 0; e < 4; e++) cfr[t][u][e] = 0.f;

    float4 aR[2], bR[2];
    const int nst = K >> 4;

#pragma unroll
    for (int it = 0; it < 2; it++) {
        aR[it] = *(const float4*)(A + (size_t)(m0 + am) * K + (akq + 2 * it) * 4);
        bR[it] = *(const float4*)(Bw + (size_t)(bk + it * 8) * N + n0 + bn4);
    }
    {
        float* AH = sm;            float* AL = sm + TILE_F;
        float* BH = sm + 2*TILE_F; float* BL = sm + 3*TILE_F;
#pragma unroll
        for (int it = 0; it < 2; it++) {
            const int k4 = (akq + 2 * it) * 4;
            const float av[4] = { aR[it].x, aR[it].y, aR[it].z, aR[it].w };
#pragma unroll
            for (int j = 0; j < 4; j++) {
                const float h = to_tf32(av[j]);
                AH[(k4 + j) * SK + am] = h;
                AL[(k4 + j) * SK + am] = to_tf32(av[j] - h);
            }
            const int kb = bk + it * 8;
            float4 h4, l4;
            h4.x = to_tf32(bR[it].x); l4.x = to_tf32(bR[it].x - h4.x);
            h4.y = to_tf32(bR[it].y); l4.y = to_tf32(bR[it].y - h4.y);
            h4.z = to_tf32(bR[it].z); l4.z = to_tf32(bR[it].z - h4.z);
            h4.w = to_tf32(bR[it].w); l4.w = to_tf32(bR[it].w - h4.w);
            *(float4*)(BH + kb * SK + bn4) = h4;
            *(float4*)(BL + kb * SK + bn4) = l4;
        }
    }
    __syncthreads();

    for (int i = 0; i < nst; i++) {
        if (i + 1 < nst) {
            const int k0 = (i + 1) << 4;
#pragma unroll
            for (int it = 0; it < 2; it++) {
                aR[it] = *(const float4*)(A + (size_t)(m0 + am) * K + k0 + (akq + 2 * it) * 4);
                bR[it] = *(const float4*)(Bw + (size_t)(k0 + bk + it * 8) * N + n0 + bn4);
            }
        }
        {
            const float* AH = sm + (size_t)(i & 1) * 4 * TILE_F;
            const float* AL = AH + TILE_F;
            const float* BH = AH + 2 * TILE_F;
            const float* BL = AH + 3 * TILE_F;
#pragma unroll
            for (int ks = 0; ks < 2; ks++) {
                const int krow = ks * 8;
                uint32_t af[4][4], bf[4][2];
#pragma unroll
                for (int t = 0; t < 4; t++) ldaf(af[t], AH, krow, wm + t * 16, lane, SK);
#pragma unroll
                for (int u = 0; u < 4; u++) ldbf(bf[u], BH, krow, wn + u * 8, lane, SK);
#pragma unroll
                for (int t = 0; t < 4; t++)
#pragma unroll
                    for (int u = 0; u < 4; u++) mma_tf32(cfr[t][u], af[t], bf[u]);
#pragma unroll
                for (int u = 0; u < 4; u++) ldbf(bf[u], BL, krow, wn + u * 8, lane, SK);
#pragma unroll
                for (int t = 0; t < 4; t++)
#pragma unroll
                    for (int u = 0; u < 4; u++) mma_tf32(cfr[t][u], af[t], bf[u]);
#pragma unroll
                for (int t = 0; t < 4; t++) ldaf(af[t], AL, krow, wm + t * 16, lane, SK);
#pragma unroll
                for (int u = 0; u < 4; u++) ldbf(bf[u], BH, krow, wn + u * 8, lane, SK);
#pragma unroll
                for (int t = 0; t < 4; t++)
#pragma unroll
                    for (int u = 0; u < 4; u++) mma_tf32(cfr[t][u], af[t], bf[u]);
            }
        }
        if (i + 1 < nst) {
            float* AH = sm + (size_t)((i + 1) & 1) * 4 * TILE_F;
            float* AL = AH + TILE_F;
            float* BH = AH + 2 * TILE_F;
            float* BL = AH + 3 * TILE_F;
#pragma unroll
            for (int it = 0; it < 2; it++) {
                const int k4 = (akq + 2 * it) * 4;
                const float av[4] = { aR[it].x, aR[it].y, aR[it].z, aR[it].w };
#pragma unroll
                for (int j = 0; j < 4; j++) {
                    const float h = to_tf32(av[j]);
                    AH[(k4 + j) * SK + am] = h;
                    AL[(k4 + j) * SK + am] = to_tf32(av[j] - h);
                }
                const int kb = bk + it * 8;
                float4 h4, l4;
                h4.x = to_tf32(bR[it].x); l4.x = to_tf32(bR[it].x - h4.x);
                h4.y = to_tf32(bR[it].y); l4.y = to_tf32(bR[it].y - h4.y);
                h4.z = to_tf32(bR[it].z); l4.z = to_tf32(bR[it].z - h4.z);
                h4.w = to_tf32(bR[it].w); l4.w = to_tf32(bR[it].w - h4.w);
                *(float4*)(BH + kb * SK + bn4) = h4;
                *(float4*)(BL + kb * SK + bn4) = l4;
            }
        }
        __syncthreads();
    }

#pragma unroll
    for (int t = 0; t < 4; t++) {
        const int r0 = m0 + wm + t * 16 + (lane >> 2);
        const int r1 = r0 + 8;
#pragma unroll
        for (int u = 0; u < 4; u++) {
            const int c = n0 + wn + u * 8 + 2 * (lane & 3);
            const float2 b2 = *(const float2*)(bias + c);
            float o0 = cfr[t][u][0] + b2.x, o1 = cfr[t][u][1] + b2.y;
            float o2 = cfr[t][u][2] + b2.x, o3 = cfr[t][u][3] + b2.y;
            if (relu) {
                o0 = fmaxf(o0, 0.f); o1 = fmaxf(o1, 0.f);
                o2 = fmaxf(o2, 0.f); o3 = fmaxf(o3, 0.f);
            }
            if (resid) {
                const float2 ra = *(const float2*)(resid + (size_t)r0 * N + c);
                const float2 rb = *(const float2*)(resid + (size_t)r1 * N + c);
                o0 += ra.x; o1 += ra.y; o2 += rb.x; o3 += rb.y;
            }
            *(float2*)(C + (size_t)r0 * N + c) = make_float2(o0, o1);
            *(float2*)(C + (size_t)r1 * N + c) = make_float2(o2, o3);
        }
    }
}

// ---------------------------------------------------------------------------
// HMMA flash attention (tf32x3). Block = 64 queries x 1 head x 1 batch.
// 4 warps x 16 queries. Key tiles of 32.
//   S = Q*K^T: A = Q frags (regs, hi/lo), B = Ks [dim][key] st 40.
//   softmax rows align with c-frag rows -> shfl xor 1,2 reductions.
//   P -> smem [key][q] st 24 (hi/lo), PV: B = Vs [key][dim] st 72 (hi/lo).
// ---------------------------------------------------------------------------
#define KT 32
// smem float offsets
#define AKS_H 0                    // [64][40]
#define AKS_L 2560
#define AVS_H 5120                 // [32][72]
#define AVS_L 7424
#define AQP   9728                 // QsH [64][72], QsL +4608; later P (per warp 1536)
#define ATT_SMEM_BYTES ((AQP + 2 * 64 * 72) * 4)   // 75776

__global__ __launch_bounds__(128) void attn_mma(
    const float* __restrict__ Q, const float* __restrict__ K,
    const float* __restrict__ V, float* __restrict__ O)
{
    extern __shared__ float sm[];
    const int qb = blockIdx.x, h = blockIdx.y, b = blockIdx.z;
    const int tid = threadIdx.x, lane = tid & 31, wid = tid >> 5;

    float* KsH = sm + AKS_H;
    float* KsL = sm + AKS_L;
    float* VsH = sm + AVS_H;
    float* VsL = sm + AVS_L;
    float* Qp  = sm + AQP;

    // ---- Q: transpose + 0.125 scale + tf32 split (one-time) ----
    {
        const int qr = tid & 63;
        const int db = (tid >> 6) * 32;
        const float* qp = Q + ((size_t)b * SS + qb * 64 + qr) * DD + h * DKK + db;
#pragma unroll
        for (int i = 0; i < 8; i++) {
            const float4 t = *(const float4*)(qp + 4 * i);
            const float vals[4] = { t.x, t.y, t.z, t.w };
#pragma unroll
            for (int j = 0; j < 4; j++) {
                const float v = vals[j] * 0.125f;
                const float hi = to_tf32(v);
                Qp[(db + 4 * i + j) * 72 + qr] = hi;
                Qp[4608 + (db + 4 * i + j) * 72 + qr] = to_tf32(v - hi);
            }
        }
    }
    __syncthreads();

    // ---- Q A-frags into registers ----
    uint32_t qh[8][4], qlo[8][4];
    const int q0w = wid * 16;
#pragma unroll
    for (int ks = 0; ks < 8; ks++) {
        ldaf(qh[ks],  Qp,        ks * 8, q0w, lane, 72);
        ldaf(qlo[ks], Qp + 4608, ks * 8, q0w, lane, 72);
    }

    float o[8][4];
#pragma unroll
    for (int u = 0; u < 8; u++)
#pragma unroll
        for (int e = 0; e < 4; e++) o[u][e] = 0.f;
    float m0 = -1e30f, m1 = -1e30f, l0 = 0.f, l1 = 0.f;

    float* Ph = Qp + wid * 1536;   // [32 key][24], 16 q cols used
    float* Pl = Ph + 768;
    const int r0  = lane >> 2;
    const int ct2 = 2 * (lane & 3);
    const int gq0 = qb * 64 + q0w + r0;

    const int ntk = (qb + 1) * 2;
    for (int kt = 0; kt < ntk; kt++) {
        __syncthreads();
        // K tile: transpose + split. key = tid&31 -> conflict-free STS.
        {
            const int key = tid & 31, db = (tid >> 5) * 16;
            const float* kp = K + ((size_t)b * SS + kt * KT + key) * DD + h * DKK + db;
#pragma unroll
            for (int i = 0; i < 4; i++) {
                const float4 t = *(const float4*)(kp + 4 * i);
                const float vals[4] = { t.x, t.y, t.z, t.w };
#pragma unroll
                for (int j = 0; j < 4; j++) {
                    const float hi = to_tf32(vals[j]);
                    KsH[(db + 4 * i + j) * 40 + key] = hi;
                    KsL[(db + 4 * i + j) * 40 + key] = to_tf32(vals[j] - hi);
                }
            }
        }
        // V tile: natural layout + split, vectorized.
        {
#pragma unroll
            for (int it = 0; it < 4; it++) {
                const int key = (tid >> 4) + it * 8;
                const int d4  = (tid & 15) * 4;
                const float4 t = *(const float4*)(V + ((size_t)b * SS + kt * KT + key) * DD + h * DKK + d4);
                float4 hi, lo;
                hi.x = to_tf32(t.x); lo.x = to_tf32(t.x - hi.x);
                hi.y = to_tf32(t.y); lo.y = to_tf32(t.y - hi.y);
                hi.z = to_tf32(t.z); lo.z = to_tf32(t.z - hi.z);
                hi.w = to_tf32(t.w); lo.w = to_tf32(t.w - hi.w);
                *(float4*)(VsH + key * 72 + d4) = hi;
                *(float4*)(VsL + key * 72 + d4) = lo;
            }
        }
        __syncthreads();

        // ---- S = Q*K^T (tf32x3) ----
        float s[4][4];
#pragma unroll
        for (int u = 0; u < 4; u++)
#pragma unroll
            for (int e = 0; e < 4; e++) s[u][e] = 0.f;
#pragma unroll
        for (int ks = 0; ks < 8; ks++) {
            uint32_t bh[4][2], bl[4][2];
#pragma unroll
            for (int u = 0; u < 4; u++) {
                ldbf(bh[u], KsH, ks * 8, u * 8, lane, 40);
                ldbf(bl[u], KsL, ks * 8, u * 8, lane, 40);
            }
#pragma unroll
            for (int u = 0; u < 4; u++) {
                mma_tf32(s[u], qh[ks],  bh[u]);
                mma_tf32(s[u], qh[ks],  bl[u]);
                mma_tf32(s[u], qlo[ks], bh[u]);
            }
        }

        // ---- causal mask (warp-uniform branch) ----
        if (kt * KT + KT - 1 > qb * 64 + q0w) {
#pragma unroll
            for (int u = 0; u < 4; u++) {
                const int c = kt * KT + u * 8 + ct2;
                if (c > gq0)         s[u][0] = -1e30f;
                if (c + 1 > gq0)     s[u][1] = -1e30f;
                if (c > gq0 + 8)     s[u][2] = -1e30f;
                if (c + 1 > gq0 + 8) s[u][3] = -1e30f;
            }
        }
        __syncwarp();   // prior PV reads of P complete before overwrite

        // ---- online softmax ----
        float rx0 = fmaxf(fmaxf(s[0][0], s[0][1]), fmaxf(s[1][0], s[1][1]));
        rx0 = fmaxf(rx0, fmaxf(fmaxf(s[2][0], s[2][1]), fmaxf(s[3][0], s[3][1])));
        float rx1 = fmaxf(fmaxf(s[0][2], s[0][3]), fmaxf(s[1][2], s[1][3]));
        rx1 = fmaxf(rx1, fmaxf(fmaxf(s[2][2], s[2][3]), fmaxf(s[3][2], s[3][3])));
        rx0 = fmaxf(rx0, __shfl_xor_sync(0xffffffffu, rx0, 1));
        rx0 = fmaxf(rx0, __shfl_xor_sync(0xffffffffu, rx0, 2));
        rx1 = fmaxf(rx1, __shfl_xor_sync(0xffffffffu, rx1, 1));
        rx1 = fmaxf(rx1, __shfl_xor_sync(0xffffffffu, rx1, 2));
        const float mn0 = fmaxf(m0, rx0), mn1 = fmaxf(m1, rx1);
        const float a0 = __expf(m0 - mn0), a1 = __expf(m1 - mn1);
        m0 = mn0; m1 = mn1;

        float ps0 = 0.f, ps1 = 0.f;
#pragma unroll
        for (int u = 0; u < 4; u++) {
            const float p0 = __expf(s[u][0] - m0);
            const float p1 = __expf(s[u][1] - m0);
            const float p2 = __expf(s[u][2] - m1);
            const float p3 = __expf(s[u][3] - m1);
            ps0 += p0 + p1; ps1 += p2 + p3;
            const int cb = u * 8 + ct2;
            float hp;
            hp = to_tf32(p0); Ph[cb * 24 + r0] = hp;           Pl[cb * 24 + r0] = to_tf32(p0 - hp);
            hp = to_tf32(p1); Ph[(cb + 1) * 24 + r0] = hp;     Pl[(cb + 1) * 24 + r0] = to_tf32(p1 - hp);
            hp = to_tf32(p2); Ph[cb * 24 + r0 + 8] = hp;       Pl[cb * 24 + r0 + 8] = to_tf32(p2 - hp);
            hp = to_tf32(p3); Ph[(cb + 1) * 24 + r0 + 8] = hp; Pl[(cb + 1) * 24 + r0 + 8] = to_tf32(p3 - hp);
        }
        ps0 += __shfl_xor_sync(0xffffffffu, ps0, 1);
        ps0 += __shfl_xor_sync(0xffffffffu, ps0, 2);
        ps1 += __shfl_xor_sync(0xffffffffu, ps1, 1);
        ps1 += __shfl_xor_sync(0xffffffffu, ps1, 2);
        l0 = l0 * a0 + ps0;
        l1 = l1 * a1 + ps1;
#pragma unroll
        for (int u = 0; u < 8; u++) {
            o[u][0] *= a0; o[u][1] *= a0; o[u][2] *= a1; o[u][3] *= a1;
        }
        __syncwarp();   // P visible to all lanes

        // ---- O += P*V (tf32x3) ----
#pragma unroll
        for (int kk = 0; kk < 4; kk++) {
            uint32_t ah[4], al[4];
            ldaf(ah, Ph, kk * 8, 0, lane, 24);
            ldaf(al, Pl, kk * 8, 0, lane, 24);
#pragma unroll
            for (int u = 0; u < 8; u++) {
                uint32_t bh2[2], bl2[2];
                ldbf(bh2, VsH, kk * 8, u * 8, lane, 72);
                ldbf(bl2, VsL, kk * 8, u * 8, lane, 72);
                mma_tf32(o[u], ah, bh2);
                mma_tf32(o[u], ah, bl2);
                mma_tf32(o[u], al, bh2);
            }
        }
    }

    const float inv0 = 1.f / l0, inv1 = 1.f / l1;
    float* op = O + ((size_t)b * SS + qb * 64 + q0w + r0) * DD + h * DKK;
#pragma unroll
    for (int u = 0; u < 8; u++) {
        const int c = u * 8 + ct2;
        *(float2*)(op + c)          = make_float2(o[u][0] * inv0, o[u][1] * inv0);
        *(float2*)(op + 8 * DD + c) = make_float2(o[u][2] * inv1, o[u][3] * inv1);
    }
}

// ---------------------------------------------------------------------------
// LayerNorm over last dim (512). One block (128 threads) per row.
// ---------------------------------------------------------------------------
__device__ __forceinline__ float block_sum(float v) {
    __shared__ float red[4];
#pragma unroll
    for (int off = 16; off; off >>= 1) v += __shfl_xor_sync(0xffffffffu, v, off);
    const int lane = threadIdx.x & 31, wid = threadIdx.x >> 5;
    if (lane == 0) red[wid] = v;
    __syncthreads();
    float r = (red[0] + red[1]) + (red[2] + red[3]);
    __syncthreads();
    return r;
}

__global__ __launch_bounds__(128) void ln_kernel(
    const float* __restrict__ X, const float* __restrict__ g,
    const float* __restrict__ be, float* __restrict__ out)
{
    const int row = blockIdx.x;
    const int tid = threadIdx.x;
    const float4 v = ((const float4*)(X + (size_t)row * DD))[tid];

    float s = block_sum(v.x + v.y + v.z + v.w);
    const float mu = s * (1.f / DD);
    const float dx = v.x - mu, dy = v.y - mu, dz = v.z - mu, dw = v.w - mu;
    float sq = block_sum(dx*dx + dy*dy + dz*dz + dw*dw);
    const float rstd = rsqrtf(sq * (1.f / DD) + 1e-5f);

    const float4 gv  = ((const float4*)g)[tid];
    const float4 bv  = ((const float4*)be)[tid];
    float4 oo;
    oo.x = dx * rstd * gv.x + bv.x;
    oo.y = dy * rstd * gv.y + bv.y;
    oo.z = dz * rstd * gv.z + bv.z;
    oo.w = dw * rstd * gv.w + bv.w;
    ((float4*)(out + (size_t)row * DD))[tid] = oo;
}

// ---------------------------------------------------------------------------
// Launch
// ---------------------------------------------------------------------------
static void run_tc_gemm(const float* A, const float* B, const float* bias,
                        const float* resid, float* C, int M, int N, int K, int relu)
{
    dim3 grid(N / 128, M / 128), block(256);
    tc_gemm<<<grid, block, SMEM_BYTES>>>(A, B, bias, resid, C, N, K, relu);
}

extern "C" void kernel_launch(void* const* d_in, const int* in_sizes, int n_in,
                              void* d_out, int out_size)
{
    (void)in_sizes; (void)n_in; (void)out_size;
    const float* x   = (const float*)d_in[0];
    // d_in[1] = mask (deterministic causal tril) — applied analytically
    const float* wq  = (const float*)d_in[2];
    const float* bq  = (const float*)d_in[3];
    const float* wk  = (const float*)d_in[4];
    const float* bk  = (const float*)d_in[5];
    const float* wv  = (const float*)d_in[6];
    const float* bv  = (const float*)d_in[7];
    const float* wo  = (const float*)d_in[8];
    const float* bo  = (const float*)d_in[9];
    const float* w1  = (const float*)d_in[10];
    const float* b1  = (const float*)d_in[11];
    const float* w2  = (const float*)d_in[12];
    const float* b2  = (const float*)d_in[13];
    const float* g1  = (const float*)d_in[14];
    const float* be1 = (const float*)d_in[15];
    const float* g2  = (const float*)d_in[16];
    const float* be2 = (const float*)d_in[17];
    float* out = (float*)d_out;

    float *q, *k, *v, *ctx, *h, *ffn;
    cudaGetSymbolAddress((void**)&q,   g_q);
    cudaGetSymbolAddress((void**)&k,   g_k);
    cudaGetSymbolAddress((void**)&v,   g_v);
    cudaGetSymbolAddress((void**)&ctx, g_ctx);
    cudaGetSymbolAddress((void**)&h,   g_h);
    cudaGetSymbolAddress((void**)&ffn, g_ffn);

    cudaFuncSetAttribute(tc_gemm,  cudaFuncAttributeMaxDynamicSharedMemorySize, SMEM_BYTES);
    cudaFuncSetAttribute(attn_mma, cudaFuncAttributeMaxDynamicSharedMemorySize, ATT_SMEM_BYTES);

    // QKV projections (HMMA tf32x3)
    run_tc_gemm(x, wq, bq, nullptr, q, MM, DD, DD, 0);
    run_tc_gemm(x, wk, bk, nullptr, k, MM, DD, DD, 0);
    run_tc_gemm(x, wv, bv, nullptr, v, MM, DD, DD, 0);

    // Causal attention (HMMA) -> ctx [B,S,D]
    attn_mma<<<dim3(SS / 64, HH, BB), 128, ATT_SMEM_BYTES>>>(q, k, v, ctx);

    // Output projection + residual (x) -> reuse q as pre-LN buffer
    run_tc_gemm(ctx, wo, bo, x, q, MM, DD, DD, 0);
    ln_kernel<<<MM, 128>>>(q, g1, be1, h);

    // FFN
    run_tc_gemm(h,   w1, b1, nullptr, ffn, MM, FFF, DD, 1);
    run_tc_gemm(ffn, w2, b2, h,       q,   MM, DD, FFF, 0);
    ln_kernel<<<MM, 128>>>(q, g2, be2, out);
}

// round 9
// speedup vs baseline: 1.9617x; 1.2492x over previous
#include <cuda_runtime.h>
#include <cuda_bf16.h>
#include <cstdint>
#include <math.h>

// Problem constants
#define BB 4
#define SS 2048
#define DD 512
#define HH 8
#define DKK 64
#define FFF 2048
#define MM (BB * SS)   // 8192 rows

// ---------------------------------------------------------------------------
// Scratch (device globals — no allocation allowed)
// ---------------------------------------------------------------------------
__device__ float g_q  [MM * DD];
__device__ float g_k  [MM * DD];
__device__ float g_v  [MM * DD];
__device__ float g_ctx[MM * DD];
__device__ float g_h  [MM * DD];
__device__ float g_ffn[MM * FFF];

// ---------------------------------------------------------------------------
// Helpers
// ---------------------------------------------------------------------------
__device__ __forceinline__ float to_tf32(float x) {
    float r; asm("cvt.rna.tf32.f32 %0, %1;" : "=f"(r) : "f"(x)); return r;
}

__device__ __forceinline__ void mma_tf32(float c[4], const uint32_t a[4], const uint32_t b[2]) {
    asm volatile(
        "mma.sync.aligned.m16n8k8.row.col.f32.tf32.tf32.f32 "
        "{%0,%1,%2,%3}, {%4,%5,%6,%7}, {%8,%9}, {%0,%1,%2,%3};"
        : "+f"(c[0]), "+f"(c[1]), "+f"(c[2]), "+f"(c[3])
        : "r"(a[0]), "r"(a[1]), "r"(a[2]), "r"(a[3]), "r"(b[0]), "r"(b[1]));
}

__device__ __forceinline__ void mma_bf16(float c[4], const uint32_t a[4], const uint32_t b[2]) {
    asm volatile(
        "mma.sync.aligned.m16n8k16.row.col.f32.bf16.bf16.f32 "
        "{%0,%1,%2,%3}, {%4,%5,%6,%7}, {%8,%9}, {%0,%1,%2,%3};"
        : "+f"(c[0]), "+f"(c[1]), "+f"(c[2]), "+f"(c[3])
        : "r"(a[0]), "r"(a[1]), "r"(a[2]), "r"(a[3]), "r"(b[0]), "r"(b[1]));
}

// bf16 hi/mid split of two floats (x -> even k slot = low half, y -> odd k)
__device__ __forceinline__ void split_pack(float x, float y, uint32_t& hi, uint32_t& mid) {
    const __nv_bfloat16 hx = __float2bfloat16(x);
    const __nv_bfloat16 hy = __float2bfloat16(y);
    const float rx = x - __bfloat162float(hx);
    const float ry = y - __bfloat162float(hy);
    __nv_bfloat162 h2; h2.x = hx; h2.y = hy;
    __nv_bfloat162 m2; m2.x = __float2bfloat16(rx); m2.y = __float2bfloat16(ry);
    hi  = *reinterpret_cast<uint32_t*>(&h2);
    mid = *reinterpret_cast<uint32_t*>(&m2);
}

// Generic fp32 fragment loaders (A stored k-major [k][m], B stored [k][n])
__device__ __forceinline__ void ldaf(uint32_t a[4], const float* base,
                                     int krow, int mrow, int lane, int st) {
    const float* p = base + (krow + (lane & 3)) * st + mrow + (lane >> 2);
    a[0] = __float_as_uint(p[0]);
    a[1] = __float_as_uint(p[8]);
    a[2] = __float_as_uint(p[4 * st]);
    a[3] = __float_as_uint(p[4 * st + 8]);
}
__device__ __forceinline__ void ldbf(uint32_t b[2], const float* base,
                                     int krow, int ncol, int lane, int st) {
    const float* p = base + (krow + (lane & 3)) * st + ncol + (lane >> 2);
    b[0] = __float_as_uint(p[0]);
    b[1] = __float_as_uint(p[4 * st]);
}

// uint32 (bf16x2 packed, k-pair rows) fragment loaders, stride 136 words
__device__ __forceinline__ void ldaf_u(uint32_t a[4], const uint32_t* base,
                                       int mrow, int lane) {
    const uint32_t* p = base + (lane & 3) * 136 + mrow + (lane >> 2);
    a[0] = p[0];
    a[1] = p[8];
    a[2] = p[4 * 136];
    a[3] = p[4 * 136 + 8];
}
__device__ __forceinline__ void ldbf_u(uint32_t b[2], const uint32_t* base,
                                       int ncol, int lane) {
    const uint32_t* p = base + (lane & 3) * 136 + ncol + (lane >> 2);
    b[0] = p[0];
    b[1] = p[4 * 136];
}

// ---------------------------------------------------------------------------
// bf16x3 HMMA GEMM: C[M,N] = A[M,K] @ B[K,N] + bias (+resid) (opt relu)
// CTA tile 128x128, BK=16, 256 threads (8 warps as 2m x 4n of 64x32 tiles).
// smem (uint32 words, per stage): AH[8][136], AM, BH[8][136], BM  = 4352 words
// Arrays hold bf16x2 packed k-pairs: word[kp][m] = {bf16(k=2kp), bf16(k=2kp+1)}
// ---------------------------------------------------------------------------
#define GW 1088                       // words per array (8*136)
#define STG_W (4 * GW)                // words per stage (4352)
#define SMEM_BYTES (2 * STG_W * 4)    // 34816 B

__global__ __launch_bounds__(256, 2) void tc_gemm(
    const float* __restrict__ A, const float* __restrict__ Bw,
    const float* __restrict__ bias, const float* __restrict__ resid,
    float* __restrict__ C, int N, int K, int relu)
{
    extern __shared__ float smf[];
    uint32_t* smu = reinterpret_cast<uint32_t*>(smf);
    const int tid  = threadIdx.x;
    const int lane = tid & 31;
    const int wid  = tid >> 5;
    const int m0 = blockIdx.y * 128, n0 = blockIdx.x * 128;
    const int wm = (wid & 1) * 64;
    const int wn = (wid >> 1) * 32;

    // staging pattern
    const int am  = tid & 127;            // A row within tile
    const int akb = (tid >> 7) * 4;       // A k base: 0 or 4 (+8 for it=1)
    const int bkp = tid >> 5;             // B k-pair row 0..7
    const int bn4 = (tid & 31) * 4;       // B col group (4 words)

    float cfr[4][4][4];
#pragma unroll
    for (int t = 0; t < 4; t++)
#pragma unroll
        for (int u = 0; u < 4; u++)
#pragma unroll
            for (int e = 0; e < 4; e++) cfr[t][u][e] = 0.f;

    float4 aR[2], bR0, bR1;
    const int nst = K >> 4;

    // ---- stage 0: load + split + store ----
#pragma unroll
    for (int it = 0; it < 2; it++)
        aR[it] = *(const float4*)(A + (size_t)(m0 + am) * K + akb + it * 8);
    bR0 = *(const float4*)(Bw + (size_t)(2 * bkp)     * N + n0 + bn4);
    bR1 = *(const float4*)(Bw + (size_t)(2 * bkp + 1) * N + n0 + bn4);
    {
        uint32_t* AH = smu;          uint32_t* AMd = smu + GW;
        uint32_t* BH = smu + 2 * GW; uint32_t* BMd = smu + 3 * GW;
#pragma unroll
        for (int it = 0; it < 2; it++) {
            const int kp0 = (akb + it * 8) >> 1;
            uint32_t h0, md0, h1, md1;
            split_pack(aR[it].x, aR[it].y, h0, md0);
            split_pack(aR[it].z, aR[it].w, h1, md1);
            AH [kp0 * 136 + am] = h0;  AMd[kp0 * 136 + am] = md0;
            AH [(kp0 + 1) * 136 + am] = h1;  AMd[(kp0 + 1) * 136 + am] = md1;
        }
        uint4 hq, mq;
        split_pack(bR0.x, bR1.x, hq.x, mq.x);
        split_pack(bR0.y, bR1.y, hq.y, mq.y);
        split_pack(bR0.z, bR1.z, hq.z, mq.z);
        split_pack(bR0.w, bR1.w, hq.w, mq.w);
        *(uint4*)(BH  + bkp * 136 + bn4) = hq;
        *(uint4*)(BMd + bkp * 136 + bn4) = mq;
    }
    __syncthreads();

    for (int i = 0; i < nst; i++) {
        // prefetch next stage into regs
        if (i + 1 < nst) {
            const int k0 = (i + 1) << 4;
#pragma unroll
            for (int it = 0; it < 2; it++)
                aR[it] = *(const float4*)(A + (size_t)(m0 + am) * K + k0 + akb + it * 8);
            bR0 = *(const float4*)(Bw + (size_t)(k0 + 2 * bkp)     * N + n0 + bn4);
            bR1 = *(const float4*)(Bw + (size_t)(k0 + 2 * bkp + 1) * N + n0 + bn4);
        }

        // compute current stage: one k16 frag-step, 3-term split
        {
            const uint32_t* buf = smu + (size_t)(i & 1) * STG_W;
            const uint32_t* AH = buf;          const uint32_t* AMd = buf + GW;
            const uint32_t* BH = buf + 2 * GW; const uint32_t* BMd = buf + 3 * GW;
            uint32_t bh[4][2], bm[4][2];
#pragma unroll
            for (int u = 0; u < 4; u++) {
                ldbf_u(bh[u], BH,  wn + u * 8, lane);
                ldbf_u(bm[u], BMd, wn + u * 8, lane);
            }
#pragma unroll
            for (int t = 0; t < 4; t++) {
                uint32_t ah[4], av[4];
                ldaf_u(ah, AH,  wm + t * 16, lane);
                ldaf_u(av, AMd, wm + t * 16, lane);
#pragma unroll
                for (int u = 0; u < 4; u++) {
                    mma_bf16(cfr[t][u], ah, bh[u]);
                    mma_bf16(cfr[t][u], ah, bm[u]);
                    mma_bf16(cfr[t][u], av, bh[u]);
                }
            }
        }

        // store next stage
        if (i + 1 < nst) {
            uint32_t* buf = smu + (size_t)((i + 1) & 1) * STG_W;
            uint32_t* AH = buf;          uint32_t* AMd = buf + GW;
            uint32_t* BH = buf + 2 * GW; uint32_t* BMd = buf + 3 * GW;
#pragma unroll
            for (int it = 0; it < 2; it++) {
                const int kp0 = (akb + it * 8) >> 1;
                uint32_t h0, md0, h1, md1;
                split_pack(aR[it].x, aR[it].y, h0, md0);
                split_pack(aR[it].z, aR[it].w, h1, md1);
                AH [kp0 * 136 + am] = h0;  AMd[kp0 * 136 + am] = md0;
                AH [(kp0 + 1) * 136 + am] = h1;  AMd[(kp0 + 1) * 136 + am] = md1;
            }
            uint4 hq, mq;
            split_pack(bR0.x, bR1.x, hq.x, mq.x);
            split_pack(bR0.y, bR1.y, hq.y, mq.y);
            split_pack(bR0.z, bR1.z, hq.z, mq.z);
            split_pack(bR0.w, bR1.w, hq.w, mq.w);
            *(uint4*)(BH  + bkp * 136 + bn4) = hq;
            *(uint4*)(BMd + bkp * 136 + bn4) = mq;
        }
        __syncthreads();
    }

    // ---- epilogue: bias (+relu) (+resid), write C ----
#pragma unroll
    for (int t = 0; t < 4; t++) {
        const int r0 = m0 + wm + t * 16 + (lane >> 2);
        const int r1 = r0 + 8;
#pragma unroll
        for (int u = 0; u < 4; u++) {
            const int c = n0 + wn + u * 8 + 2 * (lane & 3);
            const float2 b2 = *(const float2*)(bias + c);
            float o0 = cfr[t][u][0] + b2.x, o1 = cfr[t][u][1] + b2.y;
            float o2 = cfr[t][u][2] + b2.x, o3 = cfr[t][u][3] + b2.y;
            if (relu) {
                o0 = fmaxf(o0, 0.f); o1 = fmaxf(o1, 0.f);
                o2 = fmaxf(o2, 0.f); o3 = fmaxf(o3, 0.f);
            }
            if (resid) {
                const float2 ra = *(const float2*)(resid + (size_t)r0 * N + c);
                const float2 rb = *(const float2*)(resid + (size_t)r1 * N + c);
                o0 += ra.x; o1 += ra.y; o2 += rb.x; o3 += rb.y;
            }
            *(float2*)(C + (size_t)r0 * N + c) = make_float2(o0, o1);
            *(float2*)(C + (size_t)r1 * N + c) = make_float2(o2, o3);
        }
    }
}

// ---------------------------------------------------------------------------
// HMMA flash attention (tf32x3) — unchanged from round 8 (validated).
// ---------------------------------------------------------------------------
#define KT 32
#define AKS_H 0
#define AKS_L 2560
#define AVS_H 5120
#define AVS_L 7424
#define AQP   9728
#define ATT_SMEM_BYTES ((AQP + 2 * 64 * 72) * 4)   // 75776

__global__ __launch_bounds__(128) void attn_mma(
    const float* __restrict__ Q, const float* __restrict__ K,
    const float* __restrict__ V, float* __restrict__ O)
{
    extern __shared__ float smf[];
    float* sm = smf;
    const int qb = blockIdx.x, h = blockIdx.y, b = blockIdx.z;
    const int tid = threadIdx.x, lane = tid & 31, wid = tid >> 5;

    float* KsH = sm + AKS_H;
    float* KsL = sm + AKS_L;
    float* VsH = sm + AVS_H;
    float* VsL = sm + AVS_L;
    float* Qp  = sm + AQP;

    {
        const int qr = tid & 63;
        const int db = (tid >> 6) * 32;
        const float* qp = Q + ((size_t)b * SS + qb * 64 + qr) * DD + h * DKK + db;
#pragma unroll
        for (int i = 0; i < 8; i++) {
            const float4 t = *(const float4*)(qp + 4 * i);
            const float vals[4] = { t.x, t.y, t.z, t.w };
#pragma unroll
            for (int j = 0; j < 4; j++) {
                const float v = vals[j] * 0.125f;
                const float hi = to_tf32(v);
                Qp[(db + 4 * i + j) * 72 + qr] = hi;
                Qp[4608 + (db + 4 * i + j) * 72 + qr] = to_tf32(v - hi);
            }
        }
    }
    __syncthreads();

    uint32_t qh[8][4], qlo[8][4];
    const int q0w = wid * 16;
#pragma unroll
    for (int ks = 0; ks < 8; ks++) {
        ldaf(qh[ks],  Qp,        ks * 8, q0w, lane, 72);
        ldaf(qlo[ks], Qp + 4608, ks * 8, q0w, lane, 72);
    }

    float o[8][4];
#pragma unroll
    for (int u = 0; u < 8; u++)
#pragma unroll
        for (int e = 0; e < 4; e++) o[u][e] = 0.f;
    float m0 = -1e30f, m1 = -1e30f, l0 = 0.f, l1 = 0.f;

    float* Ph = Qp + wid * 1536;
    float* Pl = Ph + 768;
    const int r0  = lane >> 2;
    const int ct2 = 2 * (lane & 3);
    const int gq0 = qb * 64 + q0w + r0;

    const int ntk = (qb + 1) * 2;
    for (int kt = 0; kt < ntk; kt++) {
        __syncthreads();
        {
            const int key = tid & 31, db = (tid >> 5) * 16;
            const float* kp = K + ((size_t)b * SS + kt * KT + key) * DD + h * DKK + db;
#pragma unroll
            for (int i = 0; i < 4; i++) {
                const float4 t = *(const float4*)(kp + 4 * i);
                const float vals[4] = { t.x, t.y, t.z, t.w };
#pragma unroll
                for (int j = 0; j < 4; j++) {
                    const float hi = to_tf32(vals[j]);
                    KsH[(db + 4 * i + j) * 40 + key] = hi;
                    KsL[(db + 4 * i + j) * 40 + key] = to_tf32(vals[j] - hi);
                }
            }
        }
        {
#pragma unroll
            for (int it = 0; it < 4; it++) {
                const int key = (tid >> 4) + it * 8;
                const int d4  = (tid & 15) * 4;
                const float4 t = *(const float4*)(V + ((size_t)b * SS + kt * KT + key) * DD + h * DKK + d4);
                float4 hi, lo;
                hi.x = to_tf32(t.x); lo.x = to_tf32(t.x - hi.x);
                hi.y = to_tf32(t.y); lo.y = to_tf32(t.y - hi.y);
                hi.z = to_tf32(t.z); lo.z = to_tf32(t.z - hi.z);
                hi.w = to_tf32(t.w); lo.w = to_tf32(t.w - hi.w);
                *(float4*)(VsH + key * 72 + d4) = hi;
                *(float4*)(VsL + key * 72 + d4) = lo;
            }
        }
        __syncthreads();

        float s[4][4];
#pragma unroll
        for (int u = 0; u < 4; u++)
#pragma unroll
            for (int e = 0; e < 4; e++) s[u][e] = 0.f;
#pragma unroll
        for (int ks = 0; ks < 8; ks++) {
            uint32_t bh[4][2], bl[4][2];
#pragma unroll
            for (int u = 0; u < 4; u++) {
                ldbf(bh[u], KsH, ks * 8, u * 8, lane, 40);
                ldbf(bl[u], KsL, ks * 8, u * 8, lane, 40);
            }
#pragma unroll
            for (int u = 0; u < 4; u++) {
                mma_tf32(s[u], qh[ks],  bh[u]);
                mma_tf32(s[u], qh[ks],  bl[u]);
                mma_tf32(s[u], qlo[ks], bh[u]);
            }
        }

        if (kt * KT + KT - 1 > qb * 64 + q0w) {
#pragma unroll
            for (int u = 0; u < 4; u++) {
                const int c = kt * KT + u * 8 + ct2;
                if (c > gq0)         s[u][0] = -1e30f;
                if (c + 1 > gq0)     s[u][1] = -1e30f;
                if (c > gq0 + 8)     s[u][2] = -1e30f;
                if (c + 1 > gq0 + 8) s[u][3] = -1e30f;
            }
        }
        __syncwarp();

        float rx0 = fmaxf(fmaxf(s[0][0], s[0][1]), fmaxf(s[1][0], s[1][1]));
        rx0 = fmaxf(rx0, fmaxf(fmaxf(s[2][0], s[2][1]), fmaxf(s[3][0], s[3][1])));
        float rx1 = fmaxf(fmaxf(s[0][2], s[0][3]), fmaxf(s[1][2], s[1][3]));
        rx1 = fmaxf(rx1, fmaxf(fmaxf(s[2][2], s[2][3]), fmaxf(s[3][2], s[3][3])));
        rx0 = fmaxf(rx0, __shfl_xor_sync(0xffffffffu, rx0, 1));
        rx0 = fmaxf(rx0, __shfl_xor_sync(0xffffffffu, rx0, 2));
        rx1 = fmaxf(rx1, __shfl_xor_sync(0xffffffffu, rx1, 1));
        rx1 = fmaxf(rx1, __shfl_xor_sync(0xffffffffu, rx1, 2));
        const float mn0 = fmaxf(m0, rx0), mn1 = fmaxf(m1, rx1);
        const float a0 = __expf(m0 - mn0), a1 = __expf(m1 - mn1);
        m0 = mn0; m1 = mn1;

        float ps0 = 0.f, ps1 = 0.f;
#pragma unroll
        for (int u = 0; u < 4; u++) {
            const float p0 = __expf(s[u][0] - m0);
            const float p1 = __expf(s[u][1] - m0);
            const float p2 = __expf(s[u][2] - m1);
            const float p3 = __expf(s[u][3] - m1);
            ps0 += p0 + p1; ps1 += p2 + p3;
            const int cb = u * 8 + ct2;
            float hp;
            hp = to_tf32(p0); Ph[cb * 24 + r0] = hp;           Pl[cb * 24 + r0] = to_tf32(p0 - hp);
            hp = to_tf32(p1); Ph[(cb + 1) * 24 + r0] = hp;     Pl[(cb + 1) * 24 + r0] = to_tf32(p1 - hp);
            hp = to_tf32(p2); Ph[cb * 24 + r0 + 8] = hp;       Pl[cb * 24 + r0 + 8] = to_tf32(p2 - hp);
            hp = to_tf32(p3); Ph[(cb + 1) * 24 + r0 + 8] = hp; Pl[(cb + 1) * 24 + r0 + 8] = to_tf32(p3 - hp);
        }
        ps0 += __shfl_xor_sync(0xffffffffu, ps0, 1);
        ps0 += __shfl_xor_sync(0xffffffffu, ps0, 2);
        ps1 += __shfl_xor_sync(0xffffffffu, ps1, 1);
        ps1 += __shfl_xor_sync(0xffffffffu, ps1, 2);
        l0 = l0 * a0 + ps0;
        l1 = l1 * a1 + ps1;
#pragma unroll
        for (int u = 0; u < 8; u++) {
            o[u][0] *= a0; o[u][1] *= a0; o[u][2] *= a1; o[u][3] *= a1;
        }
        __syncwarp();

#pragma unroll
        for (int kk = 0; kk < 4; kk++) {
            uint32_t ah[4], al[4];
            ldaf(ah, Ph, kk * 8, 0, lane, 24);
            ldaf(al, Pl, kk * 8, 0, lane, 24);
#pragma unroll
            for (int u = 0; u < 8; u++) {
                uint32_t bh2[2], bl2[2];
                ldbf(bh2, VsH, kk * 8, u * 8, lane, 72);
                ldbf(bl2, VsL, kk * 8, u * 8, lane, 72);
                mma_tf32(o[u], ah, bh2);
                mma_tf32(o[u], ah, bl2);
                mma_tf32(o[u], al, bh2);
            }
        }
    }

    const float inv0 = 1.f / l0, inv1 = 1.f / l1;
    float* op = O + ((size_t)b * SS + qb * 64 + q0w + r0) * DD + h * DKK;
#pragma unroll
    for (int u = 0; u < 8; u++) {
        const int c = u * 8 + ct2;
        *(float2*)(op + c)          = make_float2(o[u][0] * inv0, o[u][1] * inv0);
        *(float2*)(op + 8 * DD + c) = make_float2(o[u][2] * inv1, o[u][3] * inv1);
    }
}

// ---------------------------------------------------------------------------
// LayerNorm over last dim (512). One block (128 threads) per row.
// ---------------------------------------------------------------------------
__device__ __forceinline__ float block_sum(float v) {
    __shared__ float red[4];
#pragma unroll
    for (int off = 16; off; off >>= 1) v += __shfl_xor_sync(0xffffffffu, v, off);
    const int lane = threadIdx.x & 31, wid = threadIdx.x >> 5;
    if (lane == 0) red[wid] = v;
    __syncthreads();
    float r = (red[0] + red[1]) + (red[2] + red[3]);
    __syncthreads();
    return r;
}

__global__ __launch_bounds__(128) void ln_kernel(
    const float* __restrict__ X, const float* __restrict__ g,
    const float* __restrict__ be, float* __restrict__ out)
{
    const int row = blockIdx.x;
    const int tid = threadIdx.x;
    const float4 v = ((const float4*)(X + (size_t)row * DD))[tid];

    float s = block_sum(v.x + v.y + v.z + v.w);
    const float mu = s * (1.f / DD);
    const float dx = v.x - mu, dy = v.y - mu, dz = v.z - mu, dw = v.w - mu;
    float sq = block_sum(dx*dx + dy*dy + dz*dz + dw*dw);
    const float rstd = rsqrtf(sq * (1.f / DD) + 1e-5f);

    const float4 gv  = ((const float4*)g)[tid];
    const float4 bv  = ((const float4*)be)[tid];
    float4 oo;
    oo.x = dx * rstd * gv.x + bv.x;
    oo.y = dy * rstd * gv.y + bv.y;
    oo.z = dz * rstd * gv.z + bv.z;
    oo.w = dw * rstd * gv.w + bv.w;
    ((float4*)(out + (size_t)row * DD))[tid] = oo;
}

// ---------------------------------------------------------------------------
// Launch
// ---------------------------------------------------------------------------
static void run_tc_gemm(const float* A, const float* B, const float* bias,
                        const float* resid, float* C, int M, int N, int K, int relu)
{
    dim3 grid(N / 128, M / 128), block(256);
    tc_gemm<<<grid, block, SMEM_BYTES>>>(A, B, bias, resid, C, N, K, relu);
}

extern "C" void kernel_launch(void* const* d_in, const int* in_sizes, int n_in,
                              void* d_out, int out_size)
{
    (void)in_sizes; (void)n_in; (void)out_size;
    const float* x   = (const float*)d_in[0];
    // d_in[1] = mask (deterministic causal tril) — applied analytically
    const float* wq  = (const float*)d_in[2];
    const float* bq  = (const float*)d_in[3];
    const float* wk  = (const float*)d_in[4];
    const float* bk  = (const float*)d_in[5];
    const float* wv  = (const float*)d_in[6];
    const float* bv  = (const float*)d_in[7];
    const float* wo  = (const float*)d_in[8];
    const float* bo  = (const float*)d_in[9];
    const float* w1  = (const float*)d_in[10];
    const float* b1  = (const float*)d_in[11];
    const float* w2  = (const float*)d_in[12];
    const float* b2  = (const float*)d_in[13];
    const float* g1  = (const float*)d_in[14];
    const float* be1 = (const float*)d_in[15];
    const float* g2  = (const float*)d_in[16];
    const float* be2 = (const float*)d_in[17];
    float* out = (float*)d_out;

    float *q, *k, *v, *ctx, *h, *ffn;
    cudaGetSymbolAddress((void**)&q,   g_q);
    cudaGetSymbolAddress((void**)&k,   g_k);
    cudaGetSymbolAddress((void**)&v,   g_v);
    cudaGetSymbolAddress((void**)&ctx, g_ctx);
    cudaGetSymbolAddress((void**)&h,   g_h);
    cudaGetSymbolAddress((void**)&ffn, g_ffn);

    cudaFuncSetAttribute(tc_gemm,  cudaFuncAttributeMaxDynamicSharedMemorySize, SMEM_BYTES);
    cudaFuncSetAttribute(attn_mma, cudaFuncAttributeMaxDynamicSharedMemorySize, ATT_SMEM_BYTES);

    // QKV projections (HMMA bf16x3)
    run_tc_gemm(x, wq, bq, nullptr, q, MM, DD, DD, 0);
    run_tc_gemm(x, wk, bk, nullptr, k, MM, DD, DD, 0);
    run_tc_gemm(x, wv, bv, nullptr, v, MM, DD, DD, 0);

    // Causal attention (HMMA tf32x3) -> ctx [B,S,D]
    attn_mma<<<dim3(SS / 64, HH, BB), 128, ATT_SMEM_BYTES>>>(q, k, v, ctx);

    // Output projection + residual (x) -> reuse q as pre-LN buffer
    run_tc_gemm(ctx, wo, bo, x, q, MM, DD, DD, 0);
    ln_kernel<<<MM, 128>>>(q, g1, be1, h);

    // FFN
    run_tc_gemm(h,   w1, b1, nullptr, ffn, MM, FFF, DD, 1);
    run_tc_gemm(ffn, w2, b2, h,       q,   MM, DD, FFF, 0);
    ln_kernel<<<MM, 128>>>(q, g2, be2, out);
}

// round 10
// speedup vs baseline: 2.2802x; 1.1623x over previous
#include <cuda_runtime.h>
#include <cuda_bf16.h>
#include <cstdint>
#include <math.h>

// Problem constants
#define BB 4
#define SS 2048
#define DD 512
#define HH 8
#define DKK 64
#define FFF 2048
#define MM (BB * SS)   // 8192 rows

// ---------------------------------------------------------------------------
// Scratch (device globals — no allocation allowed)
// ---------------------------------------------------------------------------
__device__ float g_q  [MM * DD];
__device__ float g_k  [MM * DD];
__device__ float g_v  [MM * DD];
__device__ float g_ctx[MM * DD];
__device__ float g_h  [MM * DD];
__device__ float g_ffn[MM * FFF];

// ---------------------------------------------------------------------------
// Helpers
// ---------------------------------------------------------------------------
__device__ __forceinline__ void mma_bf16(float c[4], const uint32_t a[4], const uint32_t b[2]) {
    asm volatile(
        "mma.sync.aligned.m16n8k16.row.col.f32.bf16.bf16.f32 "
        "{%0,%1,%2,%3}, {%4,%5,%6,%7}, {%8,%9}, {%0,%1,%2,%3};"
        : "+f"(c[0]), "+f"(c[1]), "+f"(c[2]), "+f"(c[3])
        : "r"(a[0]), "r"(a[1]), "r"(a[2]), "r"(a[3]), "r"(b[0]), "r"(b[1]));
}

// bf16 hi/mid split of two floats (x -> even k slot, y -> odd k slot)
__device__ __forceinline__ void split_pack(float x, float y, uint32_t& hi, uint32_t& mid) {
    const __nv_bfloat16 hx = __float2bfloat16(x);
    const __nv_bfloat16 hy = __float2bfloat16(y);
    const float rx = x - __bfloat162float(hx);
    const float ry = y - __bfloat162float(hy);
    __nv_bfloat162 h2; h2.x = hx; h2.y = hy;
    __nv_bfloat162 m2; m2.x = __float2bfloat16(rx); m2.y = __float2bfloat16(ry);
    hi  = *reinterpret_cast<uint32_t*>(&h2);
    mid = *reinterpret_cast<uint32_t*>(&m2);
}

// uint32 (bf16x2 packed k-pair rows) fragment loaders, parametric stride.
// A-frag m16n8k16: a0=[kp=lane&3][m=lane>>2], a1=m+8, a2=kp+4, a3=kp+4,m+8
__device__ __forceinline__ void ldaf_w(uint32_t a[4], const uint32_t* base,
                                       int mrow, int lane, int st) {
    const uint32_t* p = base + (lane & 3) * st + mrow + (lane >> 2);
    a[0] = p[0];
    a[1] = p[8];
    a[2] = p[4 * st];
    a[3] = p[4 * st + 8];
}
__device__ __forceinline__ void ldbf_w(uint32_t b[2], const uint32_t* base,
                                       int ncol, int lane, int st) {
    const uint32_t* p = base + (lane & 3) * st + ncol + (lane >> 2);
    b[0] = p[0];
    b[1] = p[4 * st];
}

// ---------------------------------------------------------------------------
// bf16x3 HMMA GEMM (unchanged, validated): C = A@B + bias (+resid) (opt relu)
// CTA tile 128x128, BK=16, 256 threads (8 warps as 2m x 4n of 64x32 tiles).
// ---------------------------------------------------------------------------
#define GW 1088                       // words per array (8*136)
#define STG_W (4 * GW)                // words per stage
#define SMEM_BYTES (2 * STG_W * 4)    // 34816 B

__global__ __launch_bounds__(256, 2) void tc_gemm(
    const float* __restrict__ A, const float* __restrict__ Bw,
    const float* __restrict__ bias, const float* __restrict__ resid,
    float* __restrict__ C, int N, int K, int relu)
{
    extern __shared__ float smf[];
    uint32_t* smu = reinterpret_cast<uint32_t*>(smf);
    const int tid  = threadIdx.x;
    const int lane = tid & 31;
    const int wid  = tid >> 5;
    const int m0 = blockIdx.y * 128, n0 = blockIdx.x * 128;
    const int wm = (wid & 1) * 64;
    const int wn = (wid >> 1) * 32;

    const int am  = tid & 127;
    const int akb = (tid >> 7) * 4;
    const int bkp = tid >> 5;
    const int bn4 = (tid & 31) * 4;

    float cfr[4][4][4];
#pragma unroll
    for (int t = 0; t < 4; t++)
#pragma unroll
        for (int u = 0; u < 4; u++)
#pragma unroll
            for (int e = 0; e < 4; e++) cfr[t][u][e] = 0.f;

    float4 aR[2], bR0, bR1;
    const int nst = K >> 4;

#pragma unroll
    for (int it = 0; it < 2; it++)
        aR[it] = *(const float4*)(A + (size_t)(m0 + am) * K + akb + it * 8);
    bR0 = *(const float4*)(Bw + (size_t)(2 * bkp)     * N + n0 + bn4);
    bR1 = *(const float4*)(Bw + (size_t)(2 * bkp + 1) * N + n0 + bn4);
    {
        uint32_t* AH = smu;          uint32_t* AMd = smu + GW;
        uint32_t* BH = smu + 2 * GW; uint32_t* BMd = smu + 3 * GW;
#pragma unroll
        for (int it = 0; it < 2; it++) {
            const int kp0 = (akb + it * 8) >> 1;
            uint32_t h0, md0, h1, md1;
            split_pack(aR[it].x, aR[it].y, h0, md0);
            split_pack(aR[it].z, aR[it].w, h1, md1);
            AH [kp0 * 136 + am] = h0;  AMd[kp0 * 136 + am] = md0;
            AH [(kp0 + 1) * 136 + am] = h1;  AMd[(kp0 + 1) * 136 + am] = md1;
        }
        uint4 hq, mq;
        split_pack(bR0.x, bR1.x, hq.x, mq.x);
        split_pack(bR0.y, bR1.y, hq.y, mq.y);
        split_pack(bR0.z, bR1.z, hq.z, mq.z);
        split_pack(bR0.w, bR1.w, hq.w, mq.w);
        *(uint4*)(BH  + bkp * 136 + bn4) = hq;
        *(uint4*)(BMd + bkp * 136 + bn4) = mq;
    }
    __syncthreads();

    for (int i = 0; i < nst; i++) {
        if (i + 1 < nst) {
            const int k0 = (i + 1) << 4;
#pragma unroll
            for (int it = 0; it < 2; it++)
                aR[it] = *(const float4*)(A + (size_t)(m0 + am) * K + k0 + akb + it * 8);
            bR0 = *(const float4*)(Bw + (size_t)(k0 + 2 * bkp)     * N + n0 + bn4);
            bR1 = *(const float4*)(Bw + (size_t)(k0 + 2 * bkp + 1) * N + n0 + bn4);
        }
        {
            const uint32_t* buf = smu + (size_t)(i & 1) * STG_W;
            const uint32_t* AH = buf;          const uint32_t* AMd = buf + GW;
            const uint32_t* BH = buf + 2 * GW; const uint32_t* BMd = buf + 3 * GW;
            uint32_t bh[4][2], bm[4][2];
#pragma unroll
            for (int u = 0; u < 4; u++) {
                ldbf_w(bh[u], BH,  wn + u * 8, lane, 136);
                ldbf_w(bm[u], BMd, wn + u * 8, lane, 136);
            }
#pragma unroll
            for (int t = 0; t < 4; t++) {
                uint32_t ah[4], av[4];
                ldaf_w(ah, AH,  wm + t * 16, lane, 136);
                ldaf_w(av, AMd, wm + t * 16, lane, 136);
#pragma unroll
                for (int u = 0; u < 4; u++) {
                    mma_bf16(cfr[t][u], ah, bh[u]);
                    mma_bf16(cfr[t][u], ah, bm[u]);
                    mma_bf16(cfr[t][u], av, bh[u]);
                }
            }
        }
        if (i + 1 < nst) {
            uint32_t* buf = smu + (size_t)((i + 1) & 1) * STG_W;
            uint32_t* AH = buf;          uint32_t* AMd = buf + GW;
            uint32_t* BH = buf + 2 * GW; uint32_t* BMd = buf + 3 * GW;
#pragma unroll
            for (int it = 0; it < 2; it++) {
                const int kp0 = (akb + it * 8) >> 1;
                uint32_t h0, md0, h1, md1;
                split_pack(aR[it].x, aR[it].y, h0, md0);
                split_pack(aR[it].z, aR[it].w, h1, md1);
                AH [kp0 * 136 + am] = h0;  AMd[kp0 * 136 + am] = md0;
                AH [(kp0 + 1) * 136 + am] = h1;  AMd[(kp0 + 1) * 136 + am] = md1;
            }
            uint4 hq, mq;
            split_pack(bR0.x, bR1.x, hq.x, mq.x);
            split_pack(bR0.y, bR1.y, hq.y, mq.y);
            split_pack(bR0.z, bR1.z, hq.z, mq.z);
            split_pack(bR0.w, bR1.w, hq.w, mq.w);
            *(uint4*)(BH  + bkp * 136 + bn4) = hq;
            *(uint4*)(BMd + bkp * 136 + bn4) = mq;
        }
        __syncthreads();
    }

#pragma unroll
    for (int t = 0; t < 4; t++) {
        const int r0 = m0 + wm + t * 16 + (lane >> 2);
        const int r1 = r0 + 8;
#pragma unroll
        for (int u = 0; u < 4; u++) {
            const int c = n0 + wn + u * 8 + 2 * (lane & 3);
            const float2 b2 = *(const float2*)(bias + c);
            float o0 = cfr[t][u][0] + b2.x, o1 = cfr[t][u][1] + b2.y;
            float o2 = cfr[t][u][2] + b2.x, o3 = cfr[t][u][3] + b2.y;
            if (relu) {
                o0 = fmaxf(o0, 0.f); o1 = fmaxf(o1, 0.f);
                o2 = fmaxf(o2, 0.f); o3 = fmaxf(o3, 0.f);
            }
            if (resid) {
                const float2 ra = *(const float2*)(resid + (size_t)r0 * N + c);
                const float2 rb = *(const float2*)(resid + (size_t)r1 * N + c);
                o0 += ra.x; o1 += ra.y; o2 += rb.x; o3 += rb.y;
            }
            *(float2*)(C + (size_t)r0 * N + c) = make_float2(o0, o1);
            *(float2*)(C + (size_t)r1 * N + c) = make_float2(o2, o3);
        }
    }
}

// ---------------------------------------------------------------------------
// bf16x3 HMMA flash attention. Block = 64 queries x 1 head x 1 batch.
// 4 warps x 16 queries, key tiles of 32. All operands bf16x2-packed k-pairs.
//   S = Q*K^T: A = Q frags (regs), B = Ks [kp_dim][key] st 40.   4 k16-steps.
//   PV:        A = P [kp_key][q] st 24, B = Vs [kp_key][dim] st 72. 2 k16-steps.
// Q smem region is reused for per-warp P tiles after frags are register-resident.
// ---------------------------------------------------------------------------
#define KT 32
// word offsets
#define WKH 0          // K hi  [32][40]
#define WKM 1280       // K mid
#define WVH 2560       // V hi  [16][72]
#define WVM 3712       // V mid
#define WQH 4864       // Q hi  [32][72]; later P tiles (4 warps x 768 words)
#define WQM 7168       // Q mid [32][72]
#define ATT_SMEM_BYTES (9472 * 4)   // 37888 B

__global__ __launch_bounds__(128) void attn_mma(
    const float* __restrict__ Q, const float* __restrict__ K,
    const float* __restrict__ V, float* __restrict__ O)
{
    extern __shared__ uint32_t smw[];
    const int qb = blockIdx.x, h = blockIdx.y, b = blockIdx.z;
    const int tid = threadIdx.x, lane = tid & 31, wid = tid >> 5;

    uint32_t* KH = smw + WKH;
    uint32_t* KMd = smw + WKM;
    uint32_t* VH = smw + WVH;
    uint32_t* VMd = smw + WVM;
    uint32_t* QH = smw + WQH;
    uint32_t* QMd = smw + WQM;

    // ---- Q: transpose + 0.125 scale + bf16 split (one-time) ----
    {
        const int qr = tid & 63;
        const int db = (tid >> 6) * 32;
        const float* qp = Q + ((size_t)b * SS + qb * 64 + qr) * DD + h * DKK + db;
#pragma unroll
        for (int i = 0; i < 8; i++) {
            const float4 t = *(const float4*)(qp + 4 * i);
            const int kp = (db + 4 * i) >> 1;
            uint32_t h0, m0w, h1, m1w;
            split_pack(t.x * 0.125f, t.y * 0.125f, h0, m0w);
            split_pack(t.z * 0.125f, t.w * 0.125f, h1, m1w);
            QH [kp * 72 + qr] = h0;        QMd[kp * 72 + qr] = m0w;
            QH [(kp + 1) * 72 + qr] = h1;  QMd[(kp + 1) * 72 + qr] = m1w;
        }
    }
    __syncthreads();

    // ---- Q A-frags into registers (4 k16-steps over dim 64) ----
    uint32_t qh[4][4], qm[4][4];
    const int q0w = wid * 16;
#pragma unroll
    for (int ks = 0; ks < 4; ks++) {
        ldaf_w(qh[ks], QH  + ks * 8 * 72, q0w, lane, 72);
        ldaf_w(qm[ks], QMd + ks * 8 * 72, q0w, lane, 72);
    }
    __syncthreads();   // everyone's frags loaded before P overwrites Q region

    float o[8][4];
#pragma unroll
    for (int u = 0; u < 8; u++)
#pragma unroll
        for (int e = 0; e < 4; e++) o[u][e] = 0.f;
    float m0 = -1e30f, m1 = -1e30f, l0 = 0.f, l1 = 0.f;

    uint32_t* PH = smw + WQH + wid * 768;   // [16 kp][24], 16 q cols used
    uint32_t* PM = PH + 384;
    const int r0  = lane >> 2;
    const int ct2 = 2 * (lane & 3);
    const int gq0 = qb * 64 + q0w + r0;

    const int ntk = (qb + 1) * 2;
    for (int kt = 0; kt < ntk; kt++) {
        __syncthreads();
        // K tile: transpose + split. key = tid&31 -> conflict-free STS.
        {
            const int key = tid & 31, db = (tid >> 5) * 16;
            const float* kp_ = K + ((size_t)b * SS + kt * KT + key) * DD + h * DKK + db;
#pragma unroll
            for (int i = 0; i < 4; i++) {
                const float4 t = *(const float4*)(kp_ + 4 * i);
                const int kp = (db + 4 * i) >> 1;
                uint32_t h0, m0w, h1, m1w;
                split_pack(t.x, t.y, h0, m0w);
                split_pack(t.z, t.w, h1, m1w);
                KH [kp * 40 + key] = h0;        KMd[kp * 40 + key] = m0w;
                KH [(kp + 1) * 40 + key] = h1;  KMd[(kp + 1) * 40 + key] = m1w;
            }
        }
        // V tile: pack key-pairs per dim. kp = key/2 row, 64 dims.
        {
#pragma unroll
            for (int it = 0; it < 2; it++) {
                const int kp = (tid >> 4) + it * 8;          // 0..15
                const int d4 = (tid & 15) * 4;
                const size_t vb = ((size_t)b * SS + kt * KT + 2 * kp) * DD + h * DKK + d4;
                const float4 v0 = *(const float4*)(V + vb);
                const float4 v1 = *(const float4*)(V + vb + DD);
                uint4 hq, mq;
                split_pack(v0.x, v1.x, hq.x, mq.x);
                split_pack(v0.y, v1.y, hq.y, mq.y);
                split_pack(v0.z, v1.z, hq.z, mq.z);
                split_pack(v0.w, v1.w, hq.w, mq.w);
                *(uint4*)(VH  + kp * 72 + d4) = hq;
                *(uint4*)(VMd + kp * 72 + d4) = mq;
            }
        }
        __syncthreads();

        // ---- S = Q*K^T (bf16x3, 4 k16-steps) ----
        float s[4][4];
#pragma unroll
        for (int u = 0; u < 4; u++)
#pragma unroll
            for (int e = 0; e < 4; e++) s[u][e] = 0.f;
#pragma unroll
        for (int ks = 0; ks < 4; ks++) {
            uint32_t bh[4][2], bm[4][2];
#pragma unroll
            for (int u = 0; u < 4; u++) {
                ldbf_w(bh[u], KH  + ks * 8 * 40, u * 8, lane, 40);
                ldbf_w(bm[u], KMd + ks * 8 * 40, u * 8, lane, 40);
            }
#pragma unroll
            for (int u = 0; u < 4; u++) {
                mma_bf16(s[u], qh[ks], bh[u]);
                mma_bf16(s[u], qh[ks], bm[u]);
                mma_bf16(s[u], qm[ks], bh[u]);
            }
        }

        // ---- causal mask (warp-uniform branch) ----
        if (kt * KT + KT - 1 > qb * 64 + q0w) {
#pragma unroll
            for (int u = 0; u < 4; u++) {
                const int c = kt * KT + u * 8 + ct2;
                if (c > gq0)         s[u][0] = -1e30f;
                if (c + 1 > gq0)     s[u][1] = -1e30f;
                if (c > gq0 + 8)     s[u][2] = -1e30f;
                if (c + 1 > gq0 + 8) s[u][3] = -1e30f;
            }
        }
        __syncwarp();   // prior PV reads of P complete before overwrite

        // ---- online softmax ----
        float rx0 = fmaxf(fmaxf(s[0][0], s[0][1]), fmaxf(s[1][0], s[1][1]));
        rx0 = fmaxf(rx0, fmaxf(fmaxf(s[2][0], s[2][1]), fmaxf(s[3][0], s[3][1])));
        float rx1 = fmaxf(fmaxf(s[0][2], s[0][3]), fmaxf(s[1][2], s[1][3]));
        rx1 = fmaxf(rx1, fmaxf(fmaxf(s[2][2], s[2][3]), fmaxf(s[3][2], s[3][3])));
        rx0 = fmaxf(rx0, __shfl_xor_sync(0xffffffffu, rx0, 1));
        rx0 = fmaxf(rx0, __shfl_xor_sync(0xffffffffu, rx0, 2));
        rx1 = fmaxf(rx1, __shfl_xor_sync(0xffffffffu, rx1, 1));
        rx1 = fmaxf(rx1, __shfl_xor_sync(0xffffffffu, rx1, 2));
        const float mn0 = fmaxf(m0, rx0), mn1 = fmaxf(m1, rx1);
        const float a0 = __expf(m0 - mn0), a1 = __expf(m1 - mn1);
        m0 = mn0; m1 = mn1;

        float ps0 = 0.f, ps1 = 0.f;
#pragma unroll
        for (int u = 0; u < 4; u++) {
            const float p0 = __expf(s[u][0] - m0);
            const float p1 = __expf(s[u][1] - m0);
            const float p2 = __expf(s[u][2] - m1);
            const float p3 = __expf(s[u][3] - m1);
            ps0 += p0 + p1; ps1 += p2 + p3;
            const int kpc = u * 4 + (lane & 3);   // key-pair column (c/2)
            uint32_t hh, mm;
            split_pack(p0, p1, hh, mm);
            PH[kpc * 24 + r0] = hh;      PM[kpc * 24 + r0] = mm;
            split_pack(p2, p3, hh, mm);
            PH[kpc * 24 + r0 + 8] = hh;  PM[kpc * 24 + r0 + 8] = mm;
        }
        ps0 += __shfl_xor_sync(0xffffffffu, ps0, 1);
        ps0 += __shfl_xor_sync(0xffffffffu, ps0, 2);
        ps1 += __shfl_xor_sync(0xffffffffu, ps1, 1);
        ps1 += __shfl_xor_sync(0xffffffffu, ps1, 2);
        l0 = l0 * a0 + ps0;
        l1 = l1 * a1 + ps1;
#pragma unroll
        for (int u = 0; u < 8; u++) {
            o[u][0] *= a0; o[u][1] *= a0; o[u][2] *= a1; o[u][3] *= a1;
        }
        __syncwarp();   // P visible to all lanes

        // ---- O += P*V (bf16x3, 2 k16-steps over 32 keys) ----
#pragma unroll
        for (int ks = 0; ks < 2; ks++) {
            uint32_t ah[4], am_[4];
            ldaf_w(ah,  PH + ks * 8 * 24, 0, lane, 24);
            ldaf_w(am_, PM + ks * 8 * 24, 0, lane, 24);
#pragma unroll
            for (int u = 0; u < 8; u++) {
                uint32_t bh2[2], bm2[2];
                ldbf_w(bh2, VH  + ks * 8 * 72, u * 8, lane, 72);
                ldbf_w(bm2, VMd + ks * 8 * 72, u * 8, lane, 72);
                mma_bf16(o[u], ah,  bh2);
                mma_bf16(o[u], ah,  bm2);
                mma_bf16(o[u], am_, bh2);
            }
        }
    }

    const float inv0 = 1.f / l0, inv1 = 1.f / l1;
    float* op = O + ((size_t)b * SS + qb * 64 + q0w + r0) * DD + h * DKK;
#pragma unroll
    for (int u = 0; u < 8; u++) {
        const int c = u * 8 + ct2;
        *(float2*)(op + c)          = make_float2(o[u][0] * inv0, o[u][1] * inv0);
        *(float2*)(op + 8 * DD + c) = make_float2(o[u][2] * inv1, o[u][3] * inv1);
    }
}

// ---------------------------------------------------------------------------
// LayerNorm over last dim (512). One block (128 threads) per row.
// ---------------------------------------------------------------------------
__device__ __forceinline__ float block_sum(float v) {
    __shared__ float red[4];
#pragma unroll
    for (int off = 16; off; off >>= 1) v += __shfl_xor_sync(0xffffffffu, v, off);
    const int lane = threadIdx.x & 31, wid = threadIdx.x >> 5;
    if (lane == 0) red[wid] = v;
    __syncthreads();
    float r = (red[0] + red[1]) + (red[2] + red[3]);
    __syncthreads();
    return r;
}

__global__ __launch_bounds__(128) void ln_kernel(
    const float* __restrict__ X, const float* __restrict__ g,
    const float* __restrict__ be, float* __restrict__ out)
{
    const int row = blockIdx.x;
    const int tid = threadIdx.x;
    const float4 v = ((const float4*)(X + (size_t)row * DD))[tid];

    float s = block_sum(v.x + v.y + v.z + v.w);
    const float mu = s * (1.f / DD);
    const float dx = v.x - mu, dy = v.y - mu, dz = v.z - mu, dw = v.w - mu;
    float sq = block_sum(dx*dx + dy*dy + dz*dz + dw*dw);
    const float rstd = rsqrtf(sq * (1.f / DD) + 1e-5f);

    const float4 gv  = ((const float4*)g)[tid];
    const float4 bv  = ((const float4*)be)[tid];
    float4 oo;
    oo.x = dx * rstd * gv.x + bv.x;
    oo.y = dy * rstd * gv.y + bv.y;
    oo.z = dz * rstd * gv.z + bv.z;
    oo.w = dw * rstd * gv.w + bv.w;
    ((float4*)(out + (size_t)row * DD))[tid] = oo;
}

// ---------------------------------------------------------------------------
// Launch
// ---------------------------------------------------------------------------
static void run_tc_gemm(const float* A, const float* B, const float* bias,
                        const float* resid, float* C, int M, int N, int K, int relu)
{
    dim3 grid(N / 128, M / 128), block(256);
    tc_gemm<<<grid, block, SMEM_BYTES>>>(A, B, bias, resid, C, N, K, relu);
}

extern "C" void kernel_launch(void* const* d_in, const int* in_sizes, int n_in,
                              void* d_out, int out_size)
{
    (void)in_sizes; (void)n_in; (void)out_size;
    const float* x   = (const float*)d_in[0];
    // d_in[1] = mask (deterministic causal tril) — applied analytically
    const float* wq  = (const float*)d_in[2];
    const float* bq  = (const float*)d_in[3];
    const float* wk  = (const float*)d_in[4];
    const float* bk  = (const float*)d_in[5];
    const float* wv  = (const float*)d_in[6];
    const float* bv  = (const float*)d_in[7];
    const float* wo  = (const float*)d_in[8];
    const float* bo  = (const float*)d_in[9];
    const float* w1  = (const float*)d_in[10];
    const float* b1  = (const float*)d_in[11];
    const float* w2  = (const float*)d_in[12];
    const float* b2  = (const float*)d_in[13];
    const float* g1  = (const float*)d_in[14];
    const float* be1 = (const float*)d_in[15];
    const float* g2  = (const float*)d_in[16];
    const float* be2 = (const float*)d_in[17];
    float* out = (float*)d_out;

    float *q, *k, *v, *ctx, *h, *ffn;
    cudaGetSymbolAddress((void**)&q,   g_q);
    cudaGetSymbolAddress((void**)&k,   g_k);
    cudaGetSymbolAddress((void**)&v,   g_v);
    cudaGetSymbolAddress((void**)&ctx, g_ctx);
    cudaGetSymbolAddress((void**)&h,   g_h);
    cudaGetSymbolAddress((void**)&ffn, g_ffn);

    cudaFuncSetAttribute(tc_gemm,  cudaFuncAttributeMaxDynamicSharedMemorySize, SMEM_BYTES);
    cudaFuncSetAttribute(attn_mma, cudaFuncAttributeMaxDynamicSharedMemorySize, ATT_SMEM_BYTES);

    // QKV projections (HMMA bf16x3)
    run_tc_gemm(x, wq, bq, nullptr, q, MM, DD, DD, 0);
    run_tc_gemm(x, wk, bk, nullptr, k, MM, DD, DD, 0);
    run_tc_gemm(x, wv, bv, nullptr, v, MM, DD, DD, 0);

    // Causal attention (HMMA bf16x3) -> ctx [B,S,D]
    attn_mma<<<dim3(SS / 64, HH, BB), 128, ATT_SMEM_BYTES>>>(q, k, v, ctx);

    // Output projection + residual (x) -> reuse q as pre-LN buffer
    run_tc_gemm(ctx, wo, bo, x, q, MM, DD, DD, 0);
    ln_kernel<<<MM, 128>>>(q, g1, be1, h);

    // FFN
    run_tc_gemm(h,   w1, b1, nullptr, ffn, MM, FFF, DD, 1);
    run_tc_gemm(ffn, w2, b2, h,       q,   MM, DD, FFF, 0);
    ln_kernel<<<MM, 128>>>(q, g2, be2, out);
}

// round 11
// speedup vs baseline: 2.4449x; 1.0723x over previous
#include <cuda_runtime.h>
#include <cuda_bf16.h>
#include <cstdint>
#include <math.h>

// Problem constants
#define BB 4
#define SS 2048
#define DD 512
#define HH 8
#define DKK 64
#define FFF 2048
#define MM (BB * SS)   // 8192 rows
#define QKVS 1536      // combined qkv row stride

// ---------------------------------------------------------------------------
// Scratch (device globals — no allocation allowed)
// ---------------------------------------------------------------------------
__device__ float    g_qkv[MM * QKVS];       // q|k|v fp32
__device__ float    g_t1 [MM * DD];         // pre-LN buffer
__device__ float    g_h  [MM * DD];         // post-LN1 fp32 (residual for FFN2)
__device__ uint32_t g_xp_h [MM * 256],  g_xp_m [MM * 256];    // x packed
__device__ uint32_t g_ctx_h[MM * 256],  g_ctx_m[MM * 256];    // attn out packed
__device__ uint32_t g_hp_h [MM * 256],  g_hp_m [MM * 256];    // h packed
__device__ uint32_t g_ffn_h[MM * 1024], g_ffn_m[MM * 1024];   // ffn hidden packed
__device__ uint32_t g_wqkv_h[256 * QKVS], g_wqkv_m[256 * QKVS];
__device__ uint32_t g_wo_h [256 * DD],    g_wo_m [256 * DD];
__device__ uint32_t g_w1_h [256 * FFF],   g_w1_m [256 * FFF];
__device__ uint32_t g_w2_h [1024 * DD],   g_w2_m [1024 * DD];
__device__ float    g_bqkv[QKVS];

// ---------------------------------------------------------------------------
// Helpers
// ---------------------------------------------------------------------------
__device__ __forceinline__ void mma_bf16(float c[4], const uint32_t a[4], const uint32_t b[2]) {
    asm volatile(
        "mma.sync.aligned.m16n8k16.row.col.f32.bf16.bf16.f32 "
        "{%0,%1,%2,%3}, {%4,%5,%6,%7}, {%8,%9}, {%0,%1,%2,%3};"
        : "+f"(c[0]), "+f"(c[1]), "+f"(c[2]), "+f"(c[3])
        : "r"(a[0]), "r"(a[1]), "r"(a[2]), "r"(a[3]), "r"(b[0]), "r"(b[1]));
}

// bf16 hi/mid split of two floats (x -> even k slot, y -> odd k slot)
__device__ __forceinline__ void split_pack(float x, float y, uint32_t& hi, uint32_t& mid) {
    const __nv_bfloat16 hx = __float2bfloat16(x);
    const __nv_bfloat16 hy = __float2bfloat16(y);
    const float rx = x - __bfloat162float(hx);
    const float ry = y - __bfloat162float(hy);
    __nv_bfloat162 h2; h2.x = hx; h2.y = hy;
    __nv_bfloat162 m2; m2.x = __float2bfloat16(rx); m2.y = __float2bfloat16(ry);
    hi  = *reinterpret_cast<uint32_t*>(&h2);
    mid = *reinterpret_cast<uint32_t*>(&m2);
}

// Fragment loaders on packed k-pair words (A: [kp][m], B: [kp][n])
__device__ __forceinline__ void ldaf_w(uint32_t a[4], const uint32_t* base,
                                       int mrow, int lane, int st) {
    const uint32_t* p = base + (lane & 3) * st + mrow + (lane >> 2);
    a[0] = p[0];
    a[1] = p[8];
    a[2] = p[4 * st];
    a[3] = p[4 * st + 8];
}
__device__ __forceinline__ void ldbf_w(uint32_t b[2], const uint32_t* base,
                                       int ncol, int lane, int st) {
    const uint32_t* p = base + (lane & 3) * st + ncol + (lane >> 2);
    b[0] = p[0];
    b[1] = p[4 * st];
}

// ---------------------------------------------------------------------------
// Pack kernels (run once per launch; trivial bandwidth)
// ---------------------------------------------------------------------------
// Weights [K][N] fp32 -> [K/2][ostride] packed words at column offset coff.
__global__ __launch_bounds__(256) void pack_mat(
    const float* __restrict__ W, uint32_t* __restrict__ oh, uint32_t* __restrict__ om,
    int N, int ostride, int coff)
{
    const int idx = blockIdx.x * 256 + threadIdx.x;   // over Kp*N
    const int kp = idx / N;
    const int n  = idx - kp * N;
    uint32_t h, m;
    split_pack(W[(2 * kp) * N + n], W[(2 * kp + 1) * N + n], h, m);
    oh[(size_t)kp * ostride + coff + n] = h;
    om[(size_t)kp * ostride + coff + n] = m;
}

// Activations row-major, pack along innermost dim: word i = {x[2i], x[2i+1]}.
__global__ __launch_bounds__(256) void pack_act(
    const float* __restrict__ X, uint32_t* __restrict__ oh, uint32_t* __restrict__ om)
{
    const int idx = blockIdx.x * 256 + threadIdx.x;   // over total/4 float4s
    const float4 t = ((const float4*)X)[idx];
    uint32_t h0, m0, h1, m1;
    split_pack(t.x, t.y, h0, m0);
    split_pack(t.z, t.w, h1, m1);
    oh[2 * idx] = h0; oh[2 * idx + 1] = h1;
    om[2 * idx] = m0; om[2 * idx + 1] = m1;
}

__global__ void pack_bias(const float* bq, const float* bk, const float* bv, float* out) {
    const int i = blockIdx.x * 256 + threadIdx.x;
    out[i] = (i < 512) ? bq[i] : (i < 1024) ? bk[i - 512] : bv[i - 1024];
}

// ---------------------------------------------------------------------------
// Packed-operand bf16x3 HMMA GEMM.
// A: packed [M][K/2] hi/mid. B: packed [K/2][N] hi/mid.
// Epilogue: bias (+relu) (+resid fp32); writes fp32 Cf and/or packed Ch/Cm.
// CTA tile 128x128, BK=16 (8 kp), 256 threads, 8 warps 2m x 4n.
// ---------------------------------------------------------------------------
#define GW 1088                       // words per array (8*136)
#define STG_W (4 * GW)
#define SMEM_BYTES (2 * STG_W * 4)    // 34816 B

__global__ __launch_bounds__(256, 2) void tc_gemm_p(
    const uint32_t* __restrict__ Ah, const uint32_t* __restrict__ Am,
    const uint32_t* __restrict__ Bh, const uint32_t* __restrict__ Bm,
    const float* __restrict__ bias, const float* __restrict__ resid,
    float* __restrict__ Cf, uint32_t* __restrict__ Ch, uint32_t* __restrict__ Cm,
    int N, int K, int relu)
{
    extern __shared__ uint32_t smu[];
    const int tid  = threadIdx.x;
    const int lane = tid & 31;
    const int wid  = tid >> 5;
    const int m0 = blockIdx.y * 128, n0 = blockIdx.x * 128;
    const int wm = (wid & 1) * 64;
    const int wn = (wid >> 1) * 32;
    const int Kp = K >> 1;

    const int am  = tid & 127;          // A row within tile
    const int akp = (tid >> 7) * 4;     // A kp word base (0 or 4)
    const int bkp = tid >> 5;           // B kp row (0..7)
    const int bn4 = (tid & 31) * 4;     // B col group

    float cfr[4][4][4];
#pragma unroll
    for (int t = 0; t < 4; t++)
#pragma unroll
        for (int u = 0; u < 4; u++)
#pragma unroll
            for (int e = 0; e < 4; e++) cfr[t][u][e] = 0.f;

    uint4 aH, aM, bH, bM;
    const int nst = K >> 4;

    // stage 0 load + store
    aH = *(const uint4*)(Ah + (size_t)(m0 + am) * Kp + akp);
    aM = *(const uint4*)(Am + (size_t)(m0 + am) * Kp + akp);
    bH = *(const uint4*)(Bh + (size_t)bkp * N + n0 + bn4);
    bM = *(const uint4*)(Bm + (size_t)bkp * N + n0 + bn4);
    {
        uint32_t* AH = smu;          uint32_t* AMd = smu + GW;
        uint32_t* BH = smu + 2 * GW; uint32_t* BMd = smu + 3 * GW;
        AH [(akp + 0) * 136 + am] = aH.x;  AMd[(akp + 0) * 136 + am] = aM.x;
        AH [(akp + 1) * 136 + am] = aH.y;  AMd[(akp + 1) * 136 + am] = aM.y;
        AH [(akp + 2) * 136 + am] = aH.z;  AMd[(akp + 2) * 136 + am] = aM.z;
        AH [(akp + 3) * 136 + am] = aH.w;  AMd[(akp + 3) * 136 + am] = aM.w;
        *(uint4*)(BH  + bkp * 136 + bn4) = bH;
        *(uint4*)(BMd + bkp * 136 + bn4) = bM;
    }
    __syncthreads();

    for (int i = 0; i < nst; i++) {
        if (i + 1 < nst) {
            const int kw = (i + 1) << 3;
            aH = *(const uint4*)(Ah + (size_t)(m0 + am) * Kp + kw + akp);
            aM = *(const uint4*)(Am + (size_t)(m0 + am) * Kp + kw + akp);
            bH = *(const uint4*)(Bh + (size_t)(kw + bkp) * N + n0 + bn4);
            bM = *(const uint4*)(Bm + (size_t)(kw + bkp) * N + n0 + bn4);
        }
        {
            const uint32_t* buf = smu + (size_t)(i & 1) * STG_W;
            const uint32_t* AH = buf;          const uint32_t* AMd = buf + GW;
            const uint32_t* BH = buf + 2 * GW; const uint32_t* BMd = buf + 3 * GW;
            uint32_t bh[4][2], bm[4][2];
#pragma unroll
            for (int u = 0; u < 4; u++) {
                ldbf_w(bh[u], BH,  wn + u * 8, lane, 136);
                ldbf_w(bm[u], BMd, wn + u * 8, lane, 136);
            }
#pragma unroll
            for (int t = 0; t < 4; t++) {
                uint32_t ah[4], av[4];
                ldaf_w(ah, AH,  wm + t * 16, lane, 136);
                ldaf_w(av, AMd, wm + t * 16, lane, 136);
#pragma unroll
                for (int u = 0; u < 4; u++) {
                    mma_bf16(cfr[t][u], ah, bh[u]);
                    mma_bf16(cfr[t][u], ah, bm[u]);
                    mma_bf16(cfr[t][u], av, bh[u]);
                }
            }
        }
        if (i + 1 < nst) {
            uint32_t* buf = smu + (size_t)((i + 1) & 1) * STG_W;
            uint32_t* AH = buf;          uint32_t* AMd = buf + GW;
            uint32_t* BH = buf + 2 * GW; uint32_t* BMd = buf + 3 * GW;
            AH [(akp + 0) * 136 + am] = aH.x;  AMd[(akp + 0) * 136 + am] = aM.x;
            AH [(akp + 1) * 136 + am] = aH.y;  AMd[(akp + 1) * 136 + am] = aM.y;
            AH [(akp + 2) * 136 + am] = aH.z;  AMd[(akp + 2) * 136 + am] = aM.z;
            AH [(akp + 3) * 136 + am] = aH.w;  AMd[(akp + 3) * 136 + am] = aM.w;
            *(uint4*)(BH  + bkp * 136 + bn4) = bH;
            *(uint4*)(BMd + bkp * 136 + bn4) = bM;
        }
        __syncthreads();
    }

    // ---- epilogue ----
    const int Np = N >> 1;
#pragma unroll
    for (int t = 0; t < 4; t++) {
        const int r0 = m0 + wm + t * 16 + (lane >> 2);
        const int r1 = r0 + 8;
#pragma unroll
        for (int u = 0; u < 4; u++) {
            const int c = n0 + wn + u * 8 + 2 * (lane & 3);
            const float2 b2 = *(const float2*)(bias + c);
            float o0 = cfr[t][u][0] + b2.x, o1 = cfr[t][u][1] + b2.y;
            float o2 = cfr[t][u][2] + b2.x, o3 = cfr[t][u][3] + b2.y;
            if (relu) {
                o0 = fmaxf(o0, 0.f); o1 = fmaxf(o1, 0.f);
                o2 = fmaxf(o2, 0.f); o3 = fmaxf(o3, 0.f);
            }
            if (resid) {
                const float2 ra = *(const float2*)(resid + (size_t)r0 * N + c);
                const float2 rb = *(const float2*)(resid + (size_t)r1 * N + c);
                o0 += ra.x; o1 += ra.y; o2 += rb.x; o3 += rb.y;
            }
            if (Cf) {
                *(float2*)(Cf + (size_t)r0 * N + c) = make_float2(o0, o1);
                *(float2*)(Cf + (size_t)r1 * N + c) = make_float2(o2, o3);
            }
            if (Ch) {
                const int kpc = c >> 1;
                uint32_t wh, wmid;
                split_pack(o0, o1, wh, wmid);
                Ch[(size_t)r0 * Np + kpc] = wh;  Cm[(size_t)r0 * Np + kpc] = wmid;
                split_pack(o2, o3, wh, wmid);
                Ch[(size_t)r1 * Np + kpc] = wh;  Cm[(size_t)r1 * Np + kpc] = wmid;
            }
        }
    }
}

// ---------------------------------------------------------------------------
// bf16x3 HMMA flash attention (round-10 validated core).
// Reads q/k/v from combined qkv buffer (row stride QKVS).
// Writes ctx PACKED hi/mid (consumed by O-proj GEMM).
// ---------------------------------------------------------------------------
#define KT 32
#define WKH 0
#define WKM 1280
#define WVH 2560
#define WVM 3712
#define WQH 4864
#define WQM 7168
#define ATT_SMEM_BYTES (9472 * 4)   // 37888 B

__global__ __launch_bounds__(128) void attn_mma(
    const float* __restrict__ QKV,
    uint32_t* __restrict__ CtxH, uint32_t* __restrict__ CtxM)
{
    extern __shared__ uint32_t smw[];
    const int qb = blockIdx.x, h = blockIdx.y, b = blockIdx.z;
    const int tid = threadIdx.x, lane = tid & 31, wid = tid >> 5;

    const float* Q = QKV;
    const float* K = QKV + 512;
    const float* V = QKV + 1024;

    uint32_t* KH = smw + WKH;
    uint32_t* KMd = smw + WKM;
    uint32_t* VH = smw + WVH;
    uint32_t* VMd = smw + WVM;
    uint32_t* QH = smw + WQH;
    uint32_t* QMd = smw + WQM;

    // Q: transpose + 0.125 scale + split
    {
        const int qr = tid & 63;
        const int db = (tid >> 6) * 32;
        const float* qp = Q + ((size_t)b * SS + qb * 64 + qr) * QKVS + h * DKK + db;
#pragma unroll
        for (int i = 0; i < 8; i++) {
            const float4 t = *(const float4*)(qp + 4 * i);
            const int kp = (db + 4 * i) >> 1;
            uint32_t h0, m0w, h1, m1w;
            split_pack(t.x * 0.125f, t.y * 0.125f, h0, m0w);
            split_pack(t.z * 0.125f, t.w * 0.125f, h1, m1w);
            QH [kp * 72 + qr] = h0;        QMd[kp * 72 + qr] = m0w;
            QH [(kp + 1) * 72 + qr] = h1;  QMd[(kp + 1) * 72 + qr] = m1w;
        }
    }
    __syncthreads();

    uint32_t qh[4][4], qm[4][4];
    const int q0w = wid * 16;
#pragma unroll
    for (int ks = 0; ks < 4; ks++) {
        ldaf_w(qh[ks], QH  + ks * 8 * 72, q0w, lane, 72);
        ldaf_w(qm[ks], QMd + ks * 8 * 72, q0w, lane, 72);
    }
    __syncthreads();

    float o[8][4];
#pragma unroll
    for (int u = 0; u < 8; u++)
#pragma unroll
        for (int e = 0; e < 4; e++) o[u][e] = 0.f;
    float m0 = -1e30f, m1 = -1e30f, l0 = 0.f, l1 = 0.f;

    uint32_t* PH = smw + WQH + wid * 768;
    uint32_t* PM = PH + 384;
    const int r0  = lane >> 2;
    const int ct2 = 2 * (lane & 3);
    const int gq0 = qb * 64 + q0w + r0;

    const int ntk = (qb + 1) * 2;
    for (int kt = 0; kt < ntk; kt++) {
        __syncthreads();
        {
            const int key = tid & 31, db = (tid >> 5) * 16;
            const float* kp_ = K + ((size_t)b * SS + kt * KT + key) * QKVS + h * DKK + db;
#pragma unroll
            for (int i = 0; i < 4; i++) {
                const float4 t = *(const float4*)(kp_ + 4 * i);
                const int kp = (db + 4 * i) >> 1;
                uint32_t h0, m0w, h1, m1w;
                split_pack(t.x, t.y, h0, m0w);
                split_pack(t.z, t.w, h1, m1w);
                KH [kp * 40 + key] = h0;        KMd[kp * 40 + key] = m0w;
                KH [(kp + 1) * 40 + key] = h1;  KMd[(kp + 1) * 40 + key] = m1w;
            }
        }
        {
#pragma unroll
            for (int it = 0; it < 2; it++) {
                const int kp = (tid >> 4) + it * 8;
                const int d4 = (tid & 15) * 4;
                const size_t vb = ((size_t)b * SS + kt * KT + 2 * kp) * QKVS + h * DKK + d4;
                const float4 v0 = *(const float4*)(V + vb);
                const float4 v1 = *(const float4*)(V + vb + QKVS);
                uint4 hq, mq;
                split_pack(v0.x, v1.x, hq.x, mq.x);
                split_pack(v0.y, v1.y, hq.y, mq.y);
                split_pack(v0.z, v1.z, hq.z, mq.z);
                split_pack(v0.w, v1.w, hq.w, mq.w);
                *(uint4*)(VH  + kp * 72 + d4) = hq;
                *(uint4*)(VMd + kp * 72 + d4) = mq;
            }
        }
        __syncthreads();

        float s[4][4];
#pragma unroll
        for (int u = 0; u < 4; u++)
#pragma unroll
            for (int e = 0; e < 4; e++) s[u][e] = 0.f;
#pragma unroll
        for (int ks = 0; ks < 4; ks++) {
            uint32_t bh[4][2], bm[4][2];
#pragma unroll
            for (int u = 0; u < 4; u++) {
                ldbf_w(bh[u], KH  + ks * 8 * 40, u * 8, lane, 40);
                ldbf_w(bm[u], KMd + ks * 8 * 40, u * 8, lane, 40);
            }
#pragma unroll
            for (int u = 0; u < 4; u++) {
                mma_bf16(s[u], qh[ks], bh[u]);
                mma_bf16(s[u], qh[ks], bm[u]);
                mma_bf16(s[u], qm[ks], bh[u]);
            }
        }

        if (kt * KT + KT - 1 > qb * 64 + q0w) {
#pragma unroll
            for (int u = 0; u < 4; u++) {
                const int c = kt * KT + u * 8 + ct2;
                if (c > gq0)         s[u][0] = -1e30f;
                if (c + 1 > gq0)     s[u][1] = -1e30f;
                if (c > gq0 + 8)     s[u][2] = -1e30f;
                if (c + 1 > gq0 + 8) s[u][3] = -1e30f;
            }
        }
        __syncwarp();

        float rx0 = fmaxf(fmaxf(s[0][0], s[0][1]), fmaxf(s[1][0], s[1][1]));
        rx0 = fmaxf(rx0, fmaxf(fmaxf(s[2][0], s[2][1]), fmaxf(s[3][0], s[3][1])));
        float rx1 = fmaxf(fmaxf(s[0][2], s[0][3]), fmaxf(s[1][2], s[1][3]));
        rx1 = fmaxf(rx1, fmaxf(fmaxf(s[2][2], s[2][3]), fmaxf(s[3][2], s[3][3])));
        rx0 = fmaxf(rx0, __shfl_xor_sync(0xffffffffu, rx0, 1));
        rx0 = fmaxf(rx0, __shfl_xor_sync(0xffffffffu, rx0, 2));
        rx1 = fmaxf(rx1, __shfl_xor_sync(0xffffffffu, rx1, 1));
        rx1 = fmaxf(rx1, __shfl_xor_sync(0xffffffffu, rx1, 2));
        const float mn0 = fmaxf(m0, rx0), mn1 = fmaxf(m1, rx1);
        const float a0 = __expf(m0 - mn0), a1 = __expf(m1 - mn1);
        m0 = mn0; m1 = mn1;

        float ps0 = 0.f, ps1 = 0.f;
#pragma unroll
        for (int u = 0; u < 4; u++) {
            const float p0 = __expf(s[u][0] - m0);
            const float p1 = __expf(s[u][1] - m0);
            const float p2 = __expf(s[u][2] - m1);
            const float p3 = __expf(s[u][3] - m1);
            ps0 += p0 + p1; ps1 += p2 + p3;
            const int kpc = u * 4 + (lane & 3);
            uint32_t hh, mm;
            split_pack(p0, p1, hh, mm);
            PH[kpc * 24 + r0] = hh;      PM[kpc * 24 + r0] = mm;
            split_pack(p2, p3, hh, mm);
            PH[kpc * 24 + r0 + 8] = hh;  PM[kpc * 24 + r0 + 8] = mm;
        }
        ps0 += __shfl_xor_sync(0xffffffffu, ps0, 1);
        ps0 += __shfl_xor_sync(0xffffffffu, ps0, 2);
        ps1 += __shfl_xor_sync(0xffffffffu, ps1, 1);
        ps1 += __shfl_xor_sync(0xffffffffu, ps1, 2);
        l0 = l0 * a0 + ps0;
        l1 = l1 * a1 + ps1;
#pragma unroll
        for (int u = 0; u < 8; u++) {
            o[u][0] *= a0; o[u][1] *= a0; o[u][2] *= a1; o[u][3] *= a1;
        }
        __syncwarp();

#pragma unroll
        for (int ks = 0; ks < 2; ks++) {
            uint32_t ah[4], am_[4];
            ldaf_w(ah,  PH + ks * 8 * 24, 0, lane, 24);
            ldaf_w(am_, PM + ks * 8 * 24, 0, lane, 24);
#pragma unroll
            for (int u = 0; u < 8; u++) {
                uint32_t bh2[2], bm2[2];
                ldbf_w(bh2, VH  + ks * 8 * 72, u * 8, lane, 72);
                ldbf_w(bm2, VMd + ks * 8 * 72, u * 8, lane, 72);
                mma_bf16(o[u], ah,  bh2);
                mma_bf16(o[u], ah,  bm2);
                mma_bf16(o[u], am_, bh2);
            }
        }
    }

    // Epilogue: write ctx PACKED (cols c,c+1 are one word)
    const float inv0 = 1.f / l0, inv1 = 1.f / l1;
    const size_t row0 = (size_t)b * SS + qb * 64 + q0w + r0;
#pragma unroll
    for (int u = 0; u < 8; u++) {
        const int kpc = (h * DKK + u * 8 + ct2) >> 1;
        uint32_t wh, wm;
        split_pack(o[u][0] * inv0, o[u][1] * inv0, wh, wm);
        CtxH[row0 * 256 + kpc] = wh;       CtxM[row0 * 256 + kpc] = wm;
        split_pack(o[u][2] * inv1, o[u][3] * inv1, wh, wm);
        CtxH[(row0 + 8) * 256 + kpc] = wh; CtxM[(row0 + 8) * 256 + kpc] = wm;
    }
}

// ---------------------------------------------------------------------------
// LayerNorm over last dim (512); optional packed output.
// ---------------------------------------------------------------------------
__device__ __forceinline__ float block_sum(float v) {
    __shared__ float red[4];
#pragma unroll
    for (int off = 16; off; off >>= 1) v += __shfl_xor_sync(0xffffffffu, v, off);
    const int lane = threadIdx.x & 31, wid = threadIdx.x >> 5;
    if (lane == 0) red[wid] = v;
    __syncthreads();
    float r = (red[0] + red[1]) + (red[2] + red[3]);
    __syncthreads();
    return r;
}

__global__ __launch_bounds__(128) void ln_kernel(
    const float* __restrict__ X, const float* __restrict__ g,
    const float* __restrict__ be, float* __restrict__ out,
    uint32_t* __restrict__ oph, uint32_t* __restrict__ opm)
{
    const int row = blockIdx.x;
    const int tid = threadIdx.x;
    const float4 v = ((const float4*)(X + (size_t)row * DD))[tid];

    float s = block_sum(v.x + v.y + v.z + v.w);
    const float mu = s * (1.f / DD);
    const float dx = v.x - mu, dy = v.y - mu, dz = v.z - mu, dw = v.w - mu;
    float sq = block_sum(dx*dx + dy*dy + dz*dz + dw*dw);
    const float rstd = rsqrtf(sq * (1.f / DD) + 1e-5f);

    const float4 gv  = ((const float4*)g)[tid];
    const float4 bv  = ((const float4*)be)[tid];
    float4 oo;
    oo.x = dx * rstd * gv.x + bv.x;
    oo.y = dy * rstd * gv.y + bv.y;
    oo.z = dz * rstd * gv.z + bv.z;
    oo.w = dw * rstd * gv.w + bv.w;
    ((float4*)(out + (size_t)row * DD))[tid] = oo;
    if (oph) {
        uint32_t h0, m0, h1, m1;
        split_pack(oo.x, oo.y, h0, m0);
        split_pack(oo.z, oo.w, h1, m1);
        oph[(size_t)row * 256 + 2 * tid] = h0;  oph[(size_t)row * 256 + 2 * tid + 1] = h1;
        opm[(size_t)row * 256 + 2 * tid] = m0;  opm[(size_t)row * 256 + 2 * tid + 1] = m1;
    }
}

// ---------------------------------------------------------------------------
// Launch
// ---------------------------------------------------------------------------
static void run_gemm(const uint32_t* Ah, const uint32_t* Am,
                     const uint32_t* Bh, const uint32_t* Bm,
                     const float* bias, const float* resid,
                     float* Cf, uint32_t* Ch, uint32_t* Cm,
                     int M, int N, int K, int relu)
{
    dim3 grid(N / 128, M / 128), block(256);
    tc_gemm_p<<<grid, block, SMEM_BYTES>>>(Ah, Am, Bh, Bm, bias, resid, Cf, Ch, Cm, N, K, relu);
}

extern "C" void kernel_launch(void* const* d_in, const int* in_sizes, int n_in,
                              void* d_out, int out_size)
{
    (void)in_sizes; (void)n_in; (void)out_size;
    const float* x   = (const float*)d_in[0];
    // d_in[1] = mask (deterministic causal tril) — applied analytically
    const float* wq  = (const float*)d_in[2];
    const float* bq  = (const float*)d_in[3];
    const float* wk  = (const float*)d_in[4];
    const float* bk  = (const float*)d_in[5];
    const float* wv  = (const float*)d_in[6];
    const float* bv  = (const float*)d_in[7];
    const float* wo  = (const float*)d_in[8];
    const float* bo  = (const float*)d_in[9];
    const float* w1  = (const float*)d_in[10];
    const float* b1  = (const float*)d_in[11];
    const float* w2  = (const float*)d_in[12];
    const float* b2  = (const float*)d_in[13];
    const float* g1  = (const float*)d_in[14];
    const float* be1 = (const float*)d_in[15];
    const float* g2  = (const float*)d_in[16];
    const float* be2 = (const float*)d_in[17];
    float* out = (float*)d_out;

    float *qkv, *t1, *hbuf, *bqkv;
    uint32_t *xp_h, *xp_m, *ctx_h, *ctx_m, *hp_h, *hp_m, *ffn_h, *ffn_m;
    uint32_t *wqkv_h, *wqkv_m, *wo_h, *wo_m, *w1_h, *w1_m, *w2_h, *w2_m;
    cudaGetSymbolAddress((void**)&qkv,    g_qkv);
    cudaGetSymbolAddress((void**)&t1,     g_t1);
    cudaGetSymbolAddress((void**)&hbuf,   g_h);
    cudaGetSymbolAddress((void**)&bqkv,   g_bqkv);
    cudaGetSymbolAddress((void**)&xp_h,   g_xp_h);
    cudaGetSymbolAddress((void**)&xp_m,   g_xp_m);
    cudaGetSymbolAddress((void**)&ctx_h,  g_ctx_h);
    cudaGetSymbolAddress((void**)&ctx_m,  g_ctx_m);
    cudaGetSymbolAddress((void**)&hp_h,   g_hp_h);
    cudaGetSymbolAddress((void**)&hp_m,   g_hp_m);
    cudaGetSymbolAddress((void**)&ffn_h,  g_ffn_h);
    cudaGetSymbolAddress((void**)&ffn_m,  g_ffn_m);
    cudaGetSymbolAddress((void**)&wqkv_h, g_wqkv_h);
    cudaGetSymbolAddress((void**)&wqkv_m, g_wqkv_m);
    cudaGetSymbolAddress((void**)&wo_h,   g_wo_h);
    cudaGetSymbolAddress((void**)&wo_m,   g_wo_m);
    cudaGetSymbolAddress((void**)&w1_h,   g_w1_h);
    cudaGetSymbolAddress((void**)&w1_m,   g_w1_m);
    cudaGetSymbolAddress((void**)&w2_h,   g_w2_h);
    cudaGetSymbolAddress((void**)&w2_m,   g_w2_m);

    cudaFuncSetAttribute(tc_gemm_p, cudaFuncAttributeMaxDynamicSharedMemorySize, SMEM_BYTES);
    cudaFuncSetAttribute(attn_mma,  cudaFuncAttributeMaxDynamicSharedMemorySize, ATT_SMEM_BYTES);

    // ---- pack weights + x (once per call) ----
    pack_mat<<<(256 * 512) / 256, 256>>>(wq, wqkv_h, wqkv_m, 512, QKVS, 0);
    pack_mat<<<(256 * 512) / 256, 256>>>(wk, wqkv_h, wqkv_m, 512, QKVS, 512);
    pack_mat<<<(256 * 512) / 256, 256>>>(wv, wqkv_h, wqkv_m, 512, QKVS, 1024);
    pack_mat<<<(256 * 512) / 256, 256>>>(wo, wo_h, wo_m, 512, 512, 0);
    pack_mat<<<(256 * 2048) / 256, 256>>>(w1, w1_h, w1_m, 2048, 2048, 0);
    pack_mat<<<(1024 * 512) / 256, 256>>>(w2, w2_h, w2_m, 512, 512, 0);
    pack_act<<<(MM * DD / 4) / 256, 256>>>(x, xp_h, xp_m);
    pack_bias<<<QKVS / 256, 256>>>(bq, bk, bv, bqkv);

    // ---- QKV (one combined GEMM, N=1536) ----
    run_gemm(xp_h, xp_m, wqkv_h, wqkv_m, bqkv, nullptr, qkv, nullptr, nullptr,
             MM, QKVS, DD, 0);

    // ---- attention -> packed ctx ----
    attn_mma<<<dim3(SS / 64, HH, BB), 128, ATT_SMEM_BYTES>>>(qkv, ctx_h, ctx_m);

    // ---- O-proj + residual x -> t1; LN1 -> h (fp32 + packed) ----
    run_gemm(ctx_h, ctx_m, wo_h, wo_m, bo, x, t1, nullptr, nullptr, MM, DD, DD, 0);
    ln_kernel<<<MM, 128>>>(t1, g1, be1, hbuf, hp_h, hp_m);

    // ---- FFN ----
    run_gemm(hp_h, hp_m, w1_h, w1_m, b1, nullptr, nullptr, ffn_h, ffn_m,
             MM, FFF, DD, 1);
    run_gemm(ffn_h, ffn_m, w2_h, w2_m, b2, hbuf, t1, nullptr, nullptr,
             MM, DD, FFF, 0);
    ln_kernel<<<MM, 128>>>(t1, g2, be2, out, nullptr, nullptr);
}